// round 2
// baseline (speedup 1.0000x reference)
#include <cuda_runtime.h>
#include <cuda_bf16.h>
#include <math.h>
#include <float.h>

// Problem dims
#define BATCH    16384
#define IN_C     128
#define CH       512
#define EMBED_D  6240
#define NUM_EMB  512
#define DEC_IN   64
#define DEC_H    64
#define DATA_Y   32

// Output layout (all float32): dec[B*32], diff[1], embed_ind[B], perplexity[1]
#define OUT_DIFF  (BATCH * DATA_Y)
#define OUT_IND   (OUT_DIFF + 1)
#define OUT_PERP  (OUT_IND + BATCH)

#define MAXFLAG 4096
#define MARGIN  0.5f

// ---------------- scratch (device globals; no runtime allocation) -------------
__device__ float  g_h1 [BATCH * CH];
__device__ float  g_h1x[BATCH * CH];
__device__ float  g_SU [BATCH * 1024];
__device__ float  g_ex [BATCH * DEC_IN];
__device__ float  g_MG [CH * 1024];
__device__ float  g_Wf2T[EMBED_D * CH];
__device__ float  g_bias2[1024];
__device__ float  g_e2[NUM_EMB];
__device__ double g_e2d[NUM_EMB];
__device__ float  g_beta;
__device__ int    g_counts[NUM_EMB];
__device__ double g_sum;
__device__ int    g_ind[BATCH];
// refinement state
__device__ int    g_nflag;
__device__ int    g_fb [MAXFLAG];
__device__ int    g_fk1[MAXFLAG];
__device__ int    g_fk2[MAXFLAG];
__device__ double g_S  [MAXFLAG];

// ---------------- init ----------------
__global__ void init_kernel() {
    int k = threadIdx.x;
    g_counts[k] = 0;
    #pragma unroll
    for (int r = 0; r < MAXFLAG / 512; r++) g_S[k + r * 512] = 0.0;
    if (k == 0) { g_sum = 0.0; g_nflag = 0; }
}

// ---------------- transpose Wf2 [512,6240] -> Wf2T [6240,512] ----------------
__global__ void transpose_kernel(const float* __restrict__ Wf2) {
    __shared__ float t[32][33];
    int bx = blockIdx.x * 32;
    int by = blockIdx.y * 32;
    int x0 = bx + threadIdx.x;
    #pragma unroll
    for (int r = 0; r < 32; r += 8) {
        int y = by + threadIdx.y + r;
        t[threadIdx.y + r][threadIdx.x] = Wf2[(size_t)y * EMBED_D + x0];
    }
    __syncthreads();
    int xo = by + threadIdx.x;
    #pragma unroll
    for (int r = 0; r < 32; r += 8) {
        int yo = bx + threadIdx.y + r;
        g_Wf2T[(size_t)yo * CH + xo] = t[threadIdx.x][threadIdx.y + r];
    }
}

// ------- c[k] = bf2 . embed[:,k]; e2[k] = ||embed[:,k]||^2 (fp64 accum) ------
__global__ void vq_vecs_kernel(const float* __restrict__ embed,
                               const float* __restrict__ bf2) {
    int k = blockIdx.x * blockDim.x + threadIdx.x;
    if (k >= NUM_EMB) return;
    double cc = 0.0, ee = 0.0;
    for (int d = 0; d < EMBED_D; d++) {
        double e = (double)embed[(size_t)d * NUM_EMB + k];
        cc += (double)bf2[d] * e;
        ee += e * e;
    }
    g_bias2[k] = (float)cc;
    g_e2[k]  = (float)ee;
    g_e2d[k] = ee;
}

// ---------------- g[i] = Wf2[i,:] . bf2 (fp64 accum) ----------------
__global__ void g_vec_kernel(const float* __restrict__ bf2) {
    int i = blockIdx.x * blockDim.x + threadIdx.x;
    if (i >= CH) return;
    double s = 0.0;
    for (int d = 0; d < EMBED_D; d++)
        s += (double)g_Wf2T[(size_t)d * CH + i] * (double)bf2[d];
    g_bias2[CH + i] = (float)(2.0 * s);
}

// ---------------- beta = ||bf2||^2 ----------------
__global__ void beta_kernel(const float* __restrict__ bf2) {
    __shared__ double red[256];
    double s = 0.0;
    for (int d = threadIdx.x; d < EMBED_D; d += 256) { double v = bf2[d]; s += v * v; }
    red[threadIdx.x] = s;
    __syncthreads();
    for (int t = 128; t; t >>= 1) {
        if (threadIdx.x < t) red[threadIdx.x] += red[threadIdx.x + t];
        __syncthreads();
    }
    if (threadIdx.x == 0) g_beta = (float)red[0];
}

// ---------------- generic fp32 SGEMM ----------------
#define BM 128
#define BN 128
#define BK 8
template<bool HASBIAS, bool RELU>
__global__ void sgemm_kernel(const float* __restrict__ A, const float* __restrict__ B,
                             const float* __restrict__ bias, float* __restrict__ C,
                             int M, int N, int K, int lda, int ldb, int ldc) {
    __shared__ float As[BK][BM];
    __shared__ float Bs[BK][BN];
    const int tid = threadIdx.x;
    const int m0 = blockIdx.y * BM;
    const int n0 = blockIdx.x * BN;
    const int tm = (tid / 16) * 8;
    const int tn = (tid % 16) * 8;

    float acc[8][8];
    #pragma unroll
    for (int i = 0; i < 8; i++)
        #pragma unroll
        for (int j = 0; j < 8; j++) acc[i][j] = 0.f;

    const int am = tid >> 1;
    const int ak = (tid & 1) * 4;

    for (int k0 = 0; k0 < K; k0 += BK) {
        {
            float4 v = *reinterpret_cast<const float4*>(&A[(size_t)(m0 + am) * lda + k0 + ak]);
            As[ak + 0][am] = v.x; As[ak + 1][am] = v.y;
            As[ak + 2][am] = v.z; As[ak + 3][am] = v.w;
        }
        #pragma unroll
        for (int r = 0; r < 4; r++) {
            int idx = tid + r * 256;
            int kk = idx >> 7;
            int n  = idx & 127;
            int gn = n0 + n;
            Bs[kk][n] = (gn < N) ? B[(size_t)(k0 + kk) * ldb + gn] : 0.f;
        }
        __syncthreads();
        #pragma unroll
        for (int kk = 0; kk < BK; kk++) {
            float ar[8], br[8];
            float4 a0 = *reinterpret_cast<const float4*>(&As[kk][tm]);
            float4 a1 = *reinterpret_cast<const float4*>(&As[kk][tm + 4]);
            ar[0]=a0.x; ar[1]=a0.y; ar[2]=a0.z; ar[3]=a0.w;
            ar[4]=a1.x; ar[5]=a1.y; ar[6]=a1.z; ar[7]=a1.w;
            float4 b0 = *reinterpret_cast<const float4*>(&Bs[kk][tn]);
            float4 b1 = *reinterpret_cast<const float4*>(&Bs[kk][tn + 4]);
            br[0]=b0.x; br[1]=b0.y; br[2]=b0.z; br[3]=b0.w;
            br[4]=b1.x; br[5]=b1.y; br[6]=b1.z; br[7]=b1.w;
            #pragma unroll
            for (int i = 0; i < 8; i++)
                #pragma unroll
                for (int j = 0; j < 8; j++)
                    acc[i][j] += ar[i] * br[j];
        }
        __syncthreads();
    }
    #pragma unroll
    for (int i = 0; i < 8; i++) {
        int gm = m0 + tm + i;
        #pragma unroll
        for (int j = 0; j < 8; j++) {
            int gn = n0 + tn + j;
            if (gn < N) {
                float v = acc[i][j];
                if (HASBIAS) v += bias[gn];
                if (RELU)    v = fmaxf(v, 0.f);
                C[(size_t)gm * ldc + gn] = v;
            }
        }
    }
}

// ---------- per-row top-2 argmin + flag near-ties + diff accumulation --------
__global__ void argmin_kernel(float* __restrict__ out_ind_f) {
    int warp = threadIdx.x >> 5;
    int lane = threadIdx.x & 31;
    int b = blockIdx.x * 8 + warp;

    const float* su = g_SU + (size_t)b * 1024;
    const float* h  = g_h1 + (size_t)b * CH;

    float q = 0.f;
    #pragma unroll 4
    for (int j = lane; j < CH; j += 32)
        q += su[512 + j] * h[j];
    #pragma unroll
    for (int o = 16; o; o >>= 1) q += __shfl_xor_sync(0xFFFFFFFFu, q, o);

    // per-lane top-2
    float v1 = FLT_MAX, v2 = FLT_MAX;
    int   k1 = -1, k2 = -1;
    for (int k = lane; k < NUM_EMB; k += 32) {
        float v = g_e2[k] - 2.f * su[k];
        if (v < v1 || (v == v1 && k < k1)) { v2 = v1; k2 = k1; v1 = v; k1 = k; }
        else if (v < v2 || (v == v2 && k < k2)) { v2 = v; k2 = k; }
    }
    // butterfly merge of top-2 lists
    #pragma unroll
    for (int o = 16; o; o >>= 1) {
        float ov1 = __shfl_xor_sync(0xFFFFFFFFu, v1, o);
        int   ok1 = __shfl_xor_sync(0xFFFFFFFFu, k1, o);
        float ov2 = __shfl_xor_sync(0xFFFFFFFFu, v2, o);
        int   ok2 = __shfl_xor_sync(0xFFFFFFFFu, k2, o);
        // insert (ov1, ok1)
        if (!(ov1 == v1 && ok1 == k1)) {
            if (ov1 < v1 || (ov1 == v1 && ok1 < k1)) { v2 = v1; k2 = k1; v1 = ov1; k1 = ok1; }
            else if (ov1 < v2 || (ov1 == v2 && ok1 < k2)) { v2 = ov1; k2 = ok1; }
        }
        // insert (ov2, ok2)
        if (!(ov2 == v1 && ok2 == k1)) {
            if (ov2 < v1 || (ov2 == v1 && ok2 < k1)) { v2 = v1; k2 = k1; v1 = ov2; k1 = ok2; }
            else if (ov2 < v2 || (ov2 == v2 && ok2 < k2)) { v2 = ov2; k2 = ok2; }
        }
    }
    if (lane == 0) {
        g_ind[b] = k1;
        out_ind_f[b] = (float)k1;
        atomicAdd(&g_sum, (double)(q + g_beta + v1));
        if (v2 - v1 < MARGIN && k2 >= 0) {
            int idx = atomicAdd(&g_nflag, 1);
            if (idx < MAXFLAG) {
                g_fb[idx] = b; g_fk1[idx] = k1; g_fk2[idx] = k2;
            }
        }
    }
}

// ----- refinement: accumulate S_f = sum_d pre_f(b_f,d) * (e[d,k2]-e[d,k1]) ---
#define RD 16   // d-rows per block
__global__ void refine_partial_kernel(const float* __restrict__ embed,
                                      const float* __restrict__ bf2) {
    __shared__ float wtile[RD * 512];   // 32 KB
    int d0 = blockIdx.x * RD;
    for (int i = threadIdx.x; i < RD * 512 / 4; i += 256) {
        reinterpret_cast<float4*>(wtile)[i] =
            reinterpret_cast<const float4*>(g_Wf2T + (size_t)d0 * 512)[i];
    }
    __syncthreads();
    int nf = g_nflag; if (nf > MAXFLAG) nf = MAXFLAG;
    for (int t = threadIdx.x; t < nf * RD; t += 256) {
        int f  = t >> 4;        // RD = 16
        int dl = t & (RD - 1);
        int d  = d0 + dl;
        int b  = g_fb[f];
        int kk1 = g_fk1[f], kk2 = g_fk2[f];
        const float* h = g_h1 + (size_t)b * 512;
        const float* w = &wtile[dl * 512];
        float p = bf2[d];
        #pragma unroll 8
        for (int i = 0; i < 512; i++) p += h[i] * w[i];
        double de = (double)embed[(size_t)d * NUM_EMB + kk2]
                  - (double)embed[(size_t)d * NUM_EMB + kk1];
        atomicAdd(&g_S[f], (double)p * de);
    }
}

__global__ void refine_final_kernel(float* __restrict__ out_ind_f) {
    int nf = g_nflag; if (nf > MAXFLAG) nf = MAXFLAG;
    for (int f = threadIdx.x + blockIdx.x * blockDim.x; f < nf; f += blockDim.x * gridDim.x) {
        int kk1 = g_fk1[f], kk2 = g_fk2[f];
        double delta = (g_e2d[kk2] - g_e2d[kk1]) - 2.0 * g_S[f];
        if (delta < 0.0) {
            int b = g_fb[f];
            g_ind[b] = kk2;
            out_ind_f[b] = (float)kk2;
        }
    }
}

// ---------------- counts (post-refinement) ----------------
__global__ void count_kernel() {
    __shared__ int hist[NUM_EMB];
    for (int i = threadIdx.x; i < NUM_EMB; i += 256) hist[i] = 0;
    __syncthreads();
    int i0 = blockIdx.x * 2048;
    for (int i = threadIdx.x; i < 2048; i += 256)
        atomicAdd(&hist[g_ind[i0 + i]], 1);
    __syncthreads();
    for (int i = threadIdx.x; i < NUM_EMB; i += 256)
        if (hist[i]) atomicAdd(&g_counts[i], hist[i]);
}

// ---------------- per-sample expert MLP decode ----------------
__global__ void decoder_kernel(const float* __restrict__ W1, const float* __restrict__ b1,
                               const float* __restrict__ W2, const float* __restrict__ b2,
                               float* __restrict__ out) {
    __shared__ float exs[8][64];
    __shared__ float hs [8][64];
    int warp = threadIdx.x >> 5;
    int lane = threadIdx.x & 31;
    int b = blockIdx.x * 8 + warp;

    exs[warp][lane]      = g_ex[(size_t)b * 64 + lane];
    exs[warp][lane + 32] = g_ex[(size_t)b * 64 + lane + 32];
    __syncwarp();

    int k = g_ind[b];
    const float* w1 = W1 + (size_t)k * 64 * 64;
    float h0 = b1[k * 64 + lane];
    float h1 = b1[k * 64 + lane + 32];
    #pragma unroll 8
    for (int i = 0; i < 64; i++) {
        float xi = exs[warp][i];
        h0 += xi * w1[i * 64 + lane];
        h1 += xi * w1[i * 64 + lane + 32];
    }
    hs[warp][lane]      = fmaxf(h0, 0.f);
    hs[warp][lane + 32] = fmaxf(h1, 0.f);
    __syncwarp();

    const float* w2 = W2 + (size_t)k * 64 * 32;
    float o = b2[k * 32 + lane];
    #pragma unroll 8
    for (int i = 0; i < 64; i++)
        o += hs[warp][i] * w2[i * 32 + lane];
    out[(size_t)b * 32 + lane] = o;
}

// ---------------- finalize scalars ----------------
__global__ void finalize_kernel(float* __restrict__ out) {
    __shared__ float red[512];
    int k = threadIdx.x;
    float p = (float)g_counts[k] / (float)BATCH;
    red[k] = -p * logf(p + 1e-10f);
    __syncthreads();
    for (int s = 256; s; s >>= 1) {
        if (k < s) red[k] += red[k + s];
        __syncthreads();
    }
    if (k == 0) {
        out[OUT_DIFF] = (float)(g_sum / ((double)BATCH * (double)EMBED_D));
        out[OUT_PERP] = expf(red[0]);
    }
}

// ---------------- launch ----------------
extern "C" void kernel_launch(void* const* d_in, const int* in_sizes, int n_in,
                              void* d_out, int out_size) {
    const float* x     = (const float*)d_in[0];
    const float* Wf1   = (const float*)d_in[1];
    const float* bf1   = (const float*)d_in[2];
    const float* Wf2   = (const float*)d_in[3];
    const float* bf2   = (const float*)d_in[4];
    const float* Wx1   = (const float*)d_in[5];
    const float* bx1   = (const float*)d_in[6];
    const float* Wx2   = (const float*)d_in[7];
    const float* bx2   = (const float*)d_in[8];
    const float* embed = (const float*)d_in[9];
    const float* W1    = (const float*)d_in[10];
    const float* b1    = (const float*)d_in[11];
    const float* W2    = (const float*)d_in[12];
    const float* b2    = (const float*)d_in[13];
    float* out = (float*)d_out;

    float *p_h1, *p_h1x, *p_SU, *p_ex, *p_MG, *p_bias2;
    cudaGetSymbolAddress((void**)&p_h1,   g_h1);
    cudaGetSymbolAddress((void**)&p_h1x,  g_h1x);
    cudaGetSymbolAddress((void**)&p_SU,   g_SU);
    cudaGetSymbolAddress((void**)&p_ex,   g_ex);
    cudaGetSymbolAddress((void**)&p_MG,   g_MG);
    cudaGetSymbolAddress((void**)&p_bias2,g_bias2);
    float *p_Wf2T;
    cudaGetSymbolAddress((void**)&p_Wf2T, g_Wf2T);

    init_kernel<<<1, 512>>>();
    transpose_kernel<<<dim3(EMBED_D / 32, CH / 32), dim3(32, 8)>>>(Wf2);
    vq_vecs_kernel<<<2, 256>>>(embed, bf2);
    g_vec_kernel<<<2, 256>>>(bf2);
    beta_kernel<<<1, 256>>>(bf2);

    // M = Wf2 @ embed -> MG[:, 0:512]
    sgemm_kernel<false, false><<<dim3(4, 4), 256>>>(
        Wf2, embed, nullptr, p_MG, CH, NUM_EMB, EMBED_D, EMBED_D, NUM_EMB, 1024);
    // G = Wf2 @ Wf2^T -> MG[:, 512:1024]
    sgemm_kernel<false, false><<<dim3(4, 4), 256>>>(
        Wf2, p_Wf2T, nullptr, p_MG + 512, CH, CH, EMBED_D, EMBED_D, CH, 1024);

    // h1 = relu(x @ Wf1 + bf1)
    sgemm_kernel<true, true><<<dim3(4, 128), 256>>>(
        x, Wf1, bf1, p_h1, BATCH, CH, IN_C, IN_C, CH, CH);
    // h1x = relu(x @ Wx1 + bx1)
    sgemm_kernel<true, true><<<dim3(4, 128), 256>>>(
        x, Wx1, bx1, p_h1x, BATCH, CH, IN_C, IN_C, CH, CH);

    // SU = h1 @ [M|G] + [c | 2g]
    sgemm_kernel<true, false><<<dim3(8, 128), 256>>>(
        p_h1, p_MG, p_bias2, p_SU, BATCH, 1024, CH, CH, 1024, 1024);

    // ex = h1x @ Wx2 + bx2
    sgemm_kernel<true, false><<<dim3(1, 128), 256>>>(
        p_h1x, Wx2, bx2, p_ex, BATCH, DEC_IN, CH, CH, DEC_IN, DEC_IN);

    // top-2 argmin + near-tie flagging
    argmin_kernel<<<BATCH / 8, 256>>>(out + OUT_IND);

    // exact fp64 refinement of flagged rows
    refine_partial_kernel<<<EMBED_D / RD, 256>>>(embed, bf2);
    refine_final_kernel<<<8, 256>>>(out + OUT_IND);

    // counts after refinement
    count_kernel<<<BATCH / 2048, 256>>>();

    // expert decoder -> dec
    decoder_kernel<<<BATCH / 8, 256>>>(W1, b1, W2, b2, out);

    // diff + perplexity
    finalize_kernel<<<1, 512>>>(out);
}

// round 3
// speedup vs baseline: 5.2087x; 5.2087x over previous
#include <cuda_runtime.h>
#include <cuda_bf16.h>
#include <math.h>
#include <float.h>

// Problem dims
#define BATCH    16384
#define IN_C     128
#define CH       512
#define EMBED_D  6240
#define NUM_EMB  512
#define DEC_IN   64
#define DEC_H    64
#define DATA_Y   32

// Output layout (all float32): dec[B*32], diff[1], embed_ind[B], perplexity[1]
#define OUT_DIFF  (BATCH * DATA_Y)
#define OUT_IND   (OUT_DIFF + 1)
#define OUT_PERP  (OUT_IND + BATCH)

#define MAXFLAG 4096
#define MARGIN  0.0625f

#define NSPLIT  13
#define KCHUNK  480           // 13 * 480 = 6240
#define NCHUNKD 39
#define DCHUNK  160           // 39 * 160 = 6240

// ---------------- scratch (device globals) ----------------
__device__ float  g_h1 [BATCH * CH];
__device__ float  g_h1x[BATCH * CH];
__device__ float  g_SU [BATCH * 1024];
__device__ float  g_ex [BATCH * DEC_IN];
__device__ float  g_MG [CH * 1024];
__device__ float  g_part[NSPLIT * CH * 1024];
__device__ float  g_Wf2T[EMBED_D * CH];
__device__ float  g_Bcat[EMBED_D * 1024];       // [embed | Wf2T]
__device__ float  g_bias2[1024];
__device__ float  g_e2[NUM_EMB];
__device__ double g_e2d[NUM_EMB];
__device__ float  g_beta;
__device__ int    g_counts[NUM_EMB];
__device__ double g_sum;
__device__ int    g_ind[BATCH];
__device__ double g_pc [NCHUNKD * NUM_EMB];
__device__ double g_pe2[NCHUNKD * NUM_EMB];
__device__ double g_pg [NCHUNKD * CH];
// refinement state
__device__ int    g_nflag;
__device__ int    g_fb [MAXFLAG];
__device__ int    g_fk1[MAXFLAG];
__device__ int    g_fk2[MAXFLAG];
__device__ double g_S  [MAXFLAG];

// ---------------- init ----------------
__global__ void init_kernel() {
    int k = threadIdx.x;
    g_counts[k] = 0;
    #pragma unroll
    for (int r = 0; r < MAXFLAG / 512; r++) g_S[k + r * 512] = 0.0;
    if (k == 0) { g_sum = 0.0; g_nflag = 0; }
}

// ------- transpose Wf2 [512,6240] -> Wf2T [6240,512] and Bcat[:,512:1024] ----
__global__ void transpose_kernel(const float* __restrict__ Wf2) {
    __shared__ float t[32][33];
    int bx = blockIdx.x * 32;   // d
    int by = blockIdx.y * 32;   // i
    int x0 = bx + threadIdx.x;
    #pragma unroll
    for (int r = 0; r < 32; r += 8) {
        int y = by + threadIdx.y + r;
        t[threadIdx.y + r][threadIdx.x] = Wf2[(size_t)y * EMBED_D + x0];
    }
    __syncthreads();
    int xo = by + threadIdx.x;  // i
    #pragma unroll
    for (int r = 0; r < 32; r += 8) {
        int yo = bx + threadIdx.y + r;  // d
        float v = t[threadIdx.x][threadIdx.y + r];
        g_Wf2T[(size_t)yo * CH + xo] = v;
        g_Bcat[(size_t)yo * 1024 + 512 + xo] = v;
    }
}

// ---------------- copy embed into Bcat[:, 0:512] ----------------
__global__ void copy_embed_kernel(const float* __restrict__ embed) {
    int i = blockIdx.x * 256 + threadIdx.x;   // float4 index
    float4 v = reinterpret_cast<const float4*>(embed)[i];
    int d = i >> 7;          // 128 float4 per row of 512
    int c = (i & 127);
    reinterpret_cast<float4*>(&g_Bcat[(size_t)d * 1024])[c] = v;
}

// ------- chunked c/e2 partials (fp64) ----------
__global__ void vq_partial_kernel(const float* __restrict__ embed,
                                  const float* __restrict__ bf2) {
    int k = threadIdx.x;
    int d0 = blockIdx.x * DCHUNK;
    double cc = 0.0, ee = 0.0;
    for (int d = d0; d < d0 + DCHUNK; d++) {
        double e = (double)embed[(size_t)d * NUM_EMB + k];
        cc += (double)bf2[d] * e;
        ee += e * e;
    }
    g_pc [blockIdx.x * NUM_EMB + k] = cc;
    g_pe2[blockIdx.x * NUM_EMB + k] = ee;
}

__global__ void vq_reduce_kernel() {
    int k = threadIdx.x;
    double cc = 0.0, ee = 0.0;
    for (int s = 0; s < NCHUNKD; s++) {
        cc += g_pc [s * NUM_EMB + k];
        ee += g_pe2[s * NUM_EMB + k];
    }
    g_bias2[k] = (float)cc;
    g_e2[k]  = (float)ee;
    g_e2d[k] = ee;
}

// ------- chunked g partials (fp64) ----------
__global__ void g_partial_kernel(const float* __restrict__ bf2) {
    int i = threadIdx.x;
    int d0 = blockIdx.x * DCHUNK;
    double s = 0.0;
    for (int d = d0; d < d0 + DCHUNK; d++)
        s += (double)g_Wf2T[(size_t)d * CH + i] * (double)bf2[d];
    g_pg[blockIdx.x * CH + i] = s;
}

__global__ void g_reduce_kernel() {
    int i = threadIdx.x;
    double s = 0.0;
    for (int c = 0; c < NCHUNKD; c++) s += g_pg[c * CH + i];
    g_bias2[CH + i] = (float)(2.0 * s);
}

// ---------------- beta = ||bf2||^2 ----------------
__global__ void beta_kernel(const float* __restrict__ bf2) {
    __shared__ double red[256];
    double s = 0.0;
    for (int d = threadIdx.x; d < EMBED_D; d += 256) { double v = bf2[d]; s += v * v; }
    red[threadIdx.x] = s;
    __syncthreads();
    for (int t = 128; t; t >>= 1) {
        if (threadIdx.x < t) red[threadIdx.x] += red[threadIdx.x + t];
        __syncthreads();
    }
    if (threadIdx.x == 0) g_beta = (float)red[0];
}

// ---------------- SGEMM v2: BK=16, double-buffered, reg-prefetch -------------
#define BM 128
#define BN 128
#define BK 16
template<bool HASBIAS, bool RELU, bool NGUARD, bool SPLITK>
__global__ void __launch_bounds__(256, 2)
sgemm2(const float* __restrict__ A, const float* __restrict__ B,
       const float* __restrict__ bias, float* __restrict__ C,
       int M, int N, int K, int lda, int ldb, int ldc) {
    __shared__ float As[2][BK][BM];
    __shared__ float Bs[2][BK][BN];
    const int tid = threadIdx.x;
    const int m0 = blockIdx.y * BM;
    const int n0 = blockIdx.x * BN;

    if (SPLITK) {
        int ko = blockIdx.z * KCHUNK;
        A += ko;
        B += (size_t)ko * ldb;
        C += (size_t)blockIdx.z * M * N;
        K = KCHUNK;
    }

    const int tm = (tid / 16) * 8;
    const int tn = (tid % 16) * 8;
    const int am = tid >> 1;             // 0..127
    const int ak = (tid & 1) * 8;        // 0 or 8

    float acc[8][8];
    #pragma unroll
    for (int i = 0; i < 8; i++)
        #pragma unroll
        for (int j = 0; j < 8; j++) acc[i][j] = 0.f;

    float4 pa0, pa1;             // A prefetch
    float4 pb0, pb1;             // B prefetch (aligned path)
    float  pbs[8];               // B prefetch (guarded path)
    const int bf0 = tid;         // float4 slot 0
    const int bf1 = tid + 256;   // float4 slot 1
    const int bk0 = bf0 >> 5, bn0c = (bf0 & 31) * 4;
    const int bk1 = bf1 >> 5, bn1c = (bf1 & 31) * 4;

    // prime tile 0
    {
        pa0 = *reinterpret_cast<const float4*>(&A[(size_t)(m0 + am) * lda + ak]);
        pa1 = *reinterpret_cast<const float4*>(&A[(size_t)(m0 + am) * lda + ak + 4]);
        if (!NGUARD) {
            pb0 = *reinterpret_cast<const float4*>(&B[(size_t)bk0 * ldb + n0 + bn0c]);
            pb1 = *reinterpret_cast<const float4*>(&B[(size_t)bk1 * ldb + n0 + bn1c]);
        } else {
            #pragma unroll
            for (int t = 0; t < 4; t++) {
                int gn0 = n0 + bn0c + t, gn1 = n0 + bn1c + t;
                pbs[t]     = (gn0 < N) ? B[(size_t)bk0 * ldb + gn0] : 0.f;
                pbs[t + 4] = (gn1 < N) ? B[(size_t)bk1 * ldb + gn1] : 0.f;
            }
        }
    }
    // store tile 0
    As[0][ak + 0][am] = pa0.x; As[0][ak + 1][am] = pa0.y;
    As[0][ak + 2][am] = pa0.z; As[0][ak + 3][am] = pa0.w;
    As[0][ak + 4][am] = pa1.x; As[0][ak + 5][am] = pa1.y;
    As[0][ak + 6][am] = pa1.z; As[0][ak + 7][am] = pa1.w;
    if (!NGUARD) {
        *reinterpret_cast<float4*>(&Bs[0][bk0][bn0c]) = pb0;
        *reinterpret_cast<float4*>(&Bs[0][bk1][bn1c]) = pb1;
    } else {
        #pragma unroll
        for (int t = 0; t < 4; t++) {
            Bs[0][bk0][bn0c + t] = pbs[t];
            Bs[0][bk1][bn1c + t] = pbs[t + 4];
        }
    }
    __syncthreads();

    int buf = 0;
    for (int k0 = 0; k0 < K; k0 += BK) {
        bool more = (k0 + BK) < K;
        if (more) {
            int kn = k0 + BK;
            pa0 = *reinterpret_cast<const float4*>(&A[(size_t)(m0 + am) * lda + kn + ak]);
            pa1 = *reinterpret_cast<const float4*>(&A[(size_t)(m0 + am) * lda + kn + ak + 4]);
            if (!NGUARD) {
                pb0 = *reinterpret_cast<const float4*>(&B[(size_t)(kn + bk0) * ldb + n0 + bn0c]);
                pb1 = *reinterpret_cast<const float4*>(&B[(size_t)(kn + bk1) * ldb + n0 + bn1c]);
            } else {
                #pragma unroll
                for (int t = 0; t < 4; t++) {
                    int gn0 = n0 + bn0c + t, gn1 = n0 + bn1c + t;
                    pbs[t]     = (gn0 < N) ? B[(size_t)(kn + bk0) * ldb + gn0] : 0.f;
                    pbs[t + 4] = (gn1 < N) ? B[(size_t)(kn + bk1) * ldb + gn1] : 0.f;
                }
            }
        }
        #pragma unroll
        for (int kk = 0; kk < BK; kk++) {
            float ar[8], br[8];
            float4 a0 = *reinterpret_cast<const float4*>(&As[buf][kk][tm]);
            float4 a1 = *reinterpret_cast<const float4*>(&As[buf][kk][tm + 4]);
            ar[0]=a0.x; ar[1]=a0.y; ar[2]=a0.z; ar[3]=a0.w;
            ar[4]=a1.x; ar[5]=a1.y; ar[6]=a1.z; ar[7]=a1.w;
            float4 b0 = *reinterpret_cast<const float4*>(&Bs[buf][kk][tn]);
            float4 b1 = *reinterpret_cast<const float4*>(&Bs[buf][kk][tn + 4]);
            br[0]=b0.x; br[1]=b0.y; br[2]=b0.z; br[3]=b0.w;
            br[4]=b1.x; br[5]=b1.y; br[6]=b1.z; br[7]=b1.w;
            #pragma unroll
            for (int i = 0; i < 8; i++)
                #pragma unroll
                for (int j = 0; j < 8; j++)
                    acc[i][j] += ar[i] * br[j];
        }
        if (more) {
            int nb = buf ^ 1;
            As[nb][ak + 0][am] = pa0.x; As[nb][ak + 1][am] = pa0.y;
            As[nb][ak + 2][am] = pa0.z; As[nb][ak + 3][am] = pa0.w;
            As[nb][ak + 4][am] = pa1.x; As[nb][ak + 5][am] = pa1.y;
            As[nb][ak + 6][am] = pa1.z; As[nb][ak + 7][am] = pa1.w;
            if (!NGUARD) {
                *reinterpret_cast<float4*>(&Bs[nb][bk0][bn0c]) = pb0;
                *reinterpret_cast<float4*>(&Bs[nb][bk1][bn1c]) = pb1;
            } else {
                #pragma unroll
                for (int t = 0; t < 4; t++) {
                    Bs[nb][bk0][bn0c + t] = pbs[t];
                    Bs[nb][bk1][bn1c + t] = pbs[t + 4];
                }
            }
            __syncthreads();
            buf = nb;
        }
    }

    #pragma unroll
    for (int i = 0; i < 8; i++) {
        int gm = m0 + tm + i;
        #pragma unroll
        for (int j = 0; j < 8; j++) {
            int gn = n0 + tn + j;
            if (!NGUARD || gn < N) {
                float v = acc[i][j];
                if (HASBIAS) v += bias[gn];
                if (RELU)    v = fmaxf(v, 0.f);
                C[(size_t)gm * ldc + gn] = v;
            }
        }
    }
}

// ---------------- reduce split-K partials -> g_MG ----------------
__global__ void reduce_mg_kernel() {
    int i = blockIdx.x * 256 + threadIdx.x;   // 0 .. 512*1024-1
    float s = 0.f;
    #pragma unroll
    for (int p = 0; p < NSPLIT; p++) s += g_part[(size_t)p * (CH * 1024) + i];
    g_MG[i] = s;
}

// ---------- per-row top-2 argmin + flag near-ties + diff accumulation --------
__global__ void argmin_kernel(float* __restrict__ out_ind_f) {
    int warp = threadIdx.x >> 5;
    int lane = threadIdx.x & 31;
    int b = blockIdx.x * 8 + warp;

    const float* su = g_SU + (size_t)b * 1024;
    const float* h  = g_h1 + (size_t)b * CH;

    float q = 0.f;
    #pragma unroll 4
    for (int j = lane; j < CH; j += 32)
        q += su[512 + j] * h[j];
    #pragma unroll
    for (int o = 16; o; o >>= 1) q += __shfl_xor_sync(0xFFFFFFFFu, q, o);

    float v1 = FLT_MAX, v2 = FLT_MAX;
    int   k1 = -1, k2 = -1;
    for (int k = lane; k < NUM_EMB; k += 32) {
        float v = g_e2[k] - 2.f * su[k];
        if (v < v1 || (v == v1 && k < k1)) { v2 = v1; k2 = k1; v1 = v; k1 = k; }
        else if (v < v2 || (v == v2 && k < k2)) { v2 = v; k2 = k; }
    }
    #pragma unroll
    for (int o = 16; o; o >>= 1) {
        float ov1 = __shfl_xor_sync(0xFFFFFFFFu, v1, o);
        int   ok1 = __shfl_xor_sync(0xFFFFFFFFu, k1, o);
        float ov2 = __shfl_xor_sync(0xFFFFFFFFu, v2, o);
        int   ok2 = __shfl_xor_sync(0xFFFFFFFFu, k2, o);
        if (!(ov1 == v1 && ok1 == k1)) {
            if (ov1 < v1 || (ov1 == v1 && ok1 < k1)) { v2 = v1; k2 = k1; v1 = ov1; k1 = ok1; }
            else if (ov1 < v2 || (ov1 == v2 && ok1 < k2)) { v2 = ov1; k2 = ok1; }
        }
        if (!(ov2 == v1 && ok2 == k1)) {
            if (ov2 < v1 || (ov2 == v1 && ok2 < k1)) { v2 = v1; k2 = k1; v1 = ov2; k1 = ok2; }
            else if (ov2 < v2 || (ov2 == v2 && ok2 < k2)) { v2 = ov2; k2 = ok2; }
        }
    }
    if (lane == 0) {
        g_ind[b] = k1;
        out_ind_f[b] = (float)k1;
        atomicAdd(&g_sum, (double)(q + g_beta + v1));
        if (v2 - v1 < MARGIN && k2 >= 0) {
            int idx = atomicAdd(&g_nflag, 1);
            if (idx < MAXFLAG) {
                g_fb[idx] = b; g_fk1[idx] = k1; g_fk2[idx] = k2;
            }
        }
    }
}

// ----- refinement: S_f = sum_d pre_f(b_f,d) * (e[d,k2]-e[d,k1]) ---
#define RD 16
__global__ void refine_partial_kernel(const float* __restrict__ embed,
                                      const float* __restrict__ bf2) {
    __shared__ float wtile[RD * 512];
    int d0 = blockIdx.x * RD;
    for (int i = threadIdx.x; i < RD * 512 / 4; i += 256) {
        reinterpret_cast<float4*>(wtile)[i] =
            reinterpret_cast<const float4*>(g_Wf2T + (size_t)d0 * 512)[i];
    }
    __syncthreads();
    int nf = g_nflag; if (nf > MAXFLAG) nf = MAXFLAG;
    for (int t = threadIdx.x; t < nf * RD; t += 256) {
        int f  = t >> 4;
        int dl = t & (RD - 1);
        int d  = d0 + dl;
        int b  = g_fb[f];
        int kk1 = g_fk1[f], kk2 = g_fk2[f];
        const float* h = g_h1 + (size_t)b * 512;
        const float* w = &wtile[dl * 512];
        float p = bf2[d];
        #pragma unroll 8
        for (int i = 0; i < 512; i++) p += h[i] * w[i];
        double de = (double)embed[(size_t)d * NUM_EMB + kk2]
                  - (double)embed[(size_t)d * NUM_EMB + kk1];
        atomicAdd(&g_S[f], (double)p * de);
    }
}

__global__ void refine_final_kernel(float* __restrict__ out_ind_f) {
    int nf = g_nflag; if (nf > MAXFLAG) nf = MAXFLAG;
    for (int f = threadIdx.x + blockIdx.x * blockDim.x; f < nf; f += blockDim.x * gridDim.x) {
        int kk1 = g_fk1[f], kk2 = g_fk2[f];
        double delta = (g_e2d[kk2] - g_e2d[kk1]) - 2.0 * g_S[f];
        if (delta < 0.0) {
            int b = g_fb[f];
            g_ind[b] = kk2;
            out_ind_f[b] = (float)kk2;
        }
    }
}

// ---------------- counts (post-refinement) ----------------
__global__ void count_kernel() {
    __shared__ int hist[NUM_EMB];
    for (int i = threadIdx.x; i < NUM_EMB; i += 256) hist[i] = 0;
    __syncthreads();
    int i0 = blockIdx.x * 2048;
    for (int i = threadIdx.x; i < 2048; i += 256)
        atomicAdd(&hist[g_ind[i0 + i]], 1);
    __syncthreads();
    for (int i = threadIdx.x; i < NUM_EMB; i += 256)
        if (hist[i]) atomicAdd(&g_counts[i], hist[i]);
}

// ---------------- per-sample expert MLP decode ----------------
__global__ void decoder_kernel(const float* __restrict__ W1, const float* __restrict__ b1,
                               const float* __restrict__ W2, const float* __restrict__ b2,
                               float* __restrict__ out) {
    __shared__ float exs[8][64];
    __shared__ float hs [8][64];
    int warp = threadIdx.x >> 5;
    int lane = threadIdx.x & 31;
    int b = blockIdx.x * 8 + warp;

    exs[warp][lane]      = g_ex[(size_t)b * 64 + lane];
    exs[warp][lane + 32] = g_ex[(size_t)b * 64 + lane + 32];
    __syncwarp();

    int k = g_ind[b];
    const float* w1 = W1 + (size_t)k * 64 * 64;
    float h0 = b1[k * 64 + lane];
    float h1 = b1[k * 64 + lane + 32];
    #pragma unroll 8
    for (int i = 0; i < 64; i++) {
        float xi = exs[warp][i];
        h0 += xi * w1[i * 64 + lane];
        h1 += xi * w1[i * 64 + lane + 32];
    }
    hs[warp][lane]      = fmaxf(h0, 0.f);
    hs[warp][lane + 32] = fmaxf(h1, 0.f);
    __syncwarp();

    const float* w2 = W2 + (size_t)k * 64 * 32;
    float o = b2[k * 32 + lane];
    #pragma unroll 8
    for (int i = 0; i < 64; i++)
        o += hs[warp][i] * w2[i * 32 + lane];
    out[(size_t)b * 32 + lane] = o;
}

// ---------------- finalize scalars ----------------
__global__ void finalize_kernel(float* __restrict__ out) {
    __shared__ float red[512];
    int k = threadIdx.x;
    float p = (float)g_counts[k] / (float)BATCH;
    red[k] = -p * logf(p + 1e-10f);
    __syncthreads();
    for (int s = 256; s; s >>= 1) {
        if (k < s) red[k] += red[k + s];
        __syncthreads();
    }
    if (k == 0) {
        out[OUT_DIFF] = (float)(g_sum / ((double)BATCH * (double)EMBED_D));
        out[OUT_PERP] = expf(red[0]);
    }
}

// ---------------- launch ----------------
extern "C" void kernel_launch(void* const* d_in, const int* in_sizes, int n_in,
                              void* d_out, int out_size) {
    const float* x     = (const float*)d_in[0];
    const float* Wf1   = (const float*)d_in[1];
    const float* bf1   = (const float*)d_in[2];
    const float* Wf2   = (const float*)d_in[3];
    const float* bf2   = (const float*)d_in[4];
    const float* Wx1   = (const float*)d_in[5];
    const float* bx1   = (const float*)d_in[6];
    const float* Wx2   = (const float*)d_in[7];
    const float* bx2   = (const float*)d_in[8];
    const float* embed = (const float*)d_in[9];
    const float* W1    = (const float*)d_in[10];
    const float* b1    = (const float*)d_in[11];
    const float* W2    = (const float*)d_in[12];
    const float* b2    = (const float*)d_in[13];
    float* out = (float*)d_out;

    float *p_h1, *p_h1x, *p_SU, *p_ex, *p_MG, *p_bias2, *p_part, *p_Bcat;
    cudaGetSymbolAddress((void**)&p_h1,   g_h1);
    cudaGetSymbolAddress((void**)&p_h1x,  g_h1x);
    cudaGetSymbolAddress((void**)&p_SU,   g_SU);
    cudaGetSymbolAddress((void**)&p_ex,   g_ex);
    cudaGetSymbolAddress((void**)&p_MG,   g_MG);
    cudaGetSymbolAddress((void**)&p_bias2,g_bias2);
    cudaGetSymbolAddress((void**)&p_part, g_part);
    cudaGetSymbolAddress((void**)&p_Bcat, g_Bcat);

    init_kernel<<<1, 512>>>();
    transpose_kernel<<<dim3(EMBED_D / 32, CH / 32), dim3(32, 8)>>>(Wf2);
    copy_embed_kernel<<<EMBED_D * NUM_EMB / 4 / 256, 256>>>(embed);
    vq_partial_kernel<<<NCHUNKD, 512>>>(embed, bf2);
    g_partial_kernel<<<NCHUNKD, 512>>>(bf2);
    vq_reduce_kernel<<<1, 512>>>();
    g_reduce_kernel<<<1, 512>>>();
    beta_kernel<<<1, 256>>>(bf2);

    // [M|G] = Wf2 @ [embed | Wf2^T]  (split-K, 13 chunks)
    sgemm2<false, false, false, true><<<dim3(8, 4, NSPLIT), 256>>>(
        Wf2, p_Bcat, nullptr, p_part, CH, 1024, EMBED_D, EMBED_D, 1024, 1024);
    reduce_mg_kernel<<<CH * 1024 / 256, 256>>>();

    // h1 = relu(x @ Wf1 + bf1)
    sgemm2<true, true, false, false><<<dim3(4, 128), 256>>>(
        x, Wf1, bf1, p_h1, BATCH, CH, IN_C, IN_C, CH, CH);
    // h1x = relu(x @ Wx1 + bx1)
    sgemm2<true, true, false, false><<<dim3(4, 128), 256>>>(
        x, Wx1, bx1, p_h1x, BATCH, CH, IN_C, IN_C, CH, CH);

    // SU = h1 @ [M|G] + [c | 2g]
    sgemm2<true, false, false, false><<<dim3(8, 128), 256>>>(
        p_h1, p_MG, p_bias2, p_SU, BATCH, 1024, CH, CH, 1024, 1024);

    // ex = h1x @ Wx2 + bx2
    sgemm2<true, false, true, false><<<dim3(1, 128), 256>>>(
        p_h1x, Wx2, bx2, p_ex, BATCH, DEC_IN, CH, CH, DEC_IN, DEC_IN);

    // top-2 argmin + near-tie flagging
    argmin_kernel<<<BATCH / 8, 256>>>(out + OUT_IND);

    // exact fp64 refinement of flagged rows
    refine_partial_kernel<<<EMBED_D / RD, 256>>>(embed, bf2);
    refine_final_kernel<<<8, 256>>>(out + OUT_IND);

    // counts after refinement
    count_kernel<<<BATCH / 2048, 256>>>();

    // expert decoder -> dec
    decoder_kernel<<<BATCH / 8, 256>>>(W1, b1, W2, b2, out);

    // diff + perplexity
    finalize_kernel<<<1, 512>>>(out);
}

// round 5
// speedup vs baseline: 7.8801x; 1.5129x over previous
#include <cuda_runtime.h>
#include <cuda_bf16.h>
#include <math.h>
#include <float.h>
#include <stdint.h>

// Problem dims
#define BATCH    16384
#define IN_C     128
#define CH       512
#define EMBED_D  6240
#define NUM_EMB  512
#define DEC_IN   64
#define DATA_Y   32

// Output layout (float32): dec[B*32], diff[1], embed_ind[B], perplexity[1]
#define OUT_DIFF  (BATCH * DATA_Y)
#define OUT_IND   (OUT_DIFF + 1)
#define OUT_PERP  (OUT_IND + BATCH)

#define MAXFLAG 16384
#define MARGIN  2.0f

#define NSPLIT  26
#define KCHUNK  240           // 26 * 240 = 6240  (MG GEMM split-K)
#define NCHUNKD 195
#define DCHUNK  32            // 195 * 32 = 6240  (fp64 prep chunks)

// ---------------- scratch (device globals) ----------------
__device__ float  g_h1cat[BATCH * 1024];        // [h1 | h1x]
__device__ float  g_SU [BATCH * 1024];          // [s | u]
__device__ float  g_ex [BATCH * DEC_IN];
__device__ float  g_part[NSPLIT * CH * 1024];
__device__ float  g_MGT [1024 * CH];            // row n = column n of [M|G]
__device__ float  g_Wf2T[EMBED_D * CH];
__device__ float  g_Bcat[EMBED_D * 1024];       // [embed | Wf2T]
__device__ float  g_Bcat1[IN_C * 1024];         // [Wf1 | Wx1]
__device__ float  g_biascat1[1024];             // [bf1 | bx1]
__device__ float  g_bias2[1024];                // [c | 2g]
__device__ float  g_e2[NUM_EMB];
__device__ double g_e2d[NUM_EMB];
__device__ double g_cd[NUM_EMB];
__device__ float  g_beta;
__device__ int    g_counts[NUM_EMB];
__device__ double g_sum;
__device__ int    g_ind[BATCH];
__device__ double g_pc [NCHUNKD * NUM_EMB];
__device__ double g_pe2[NCHUNKD * NUM_EMB];
__device__ double g_pg [NCHUNKD * CH];
// refinement state
__device__ int    g_nflag;
__device__ int    g_fb [MAXFLAG];
__device__ int    g_fk1[MAXFLAG];
__device__ int    g_fk2[MAXFLAG];

__device__ __forceinline__ uint32_t f2tf32(float x) {
    uint32_t u;
    asm("cvt.rna.tf32.f32 %0, %1;" : "=r"(u) : "f"(x));
    return u;
}
__device__ __forceinline__ void mma8(float* c, const uint32_t* a,
                                     uint32_t b0, uint32_t b1) {
    asm volatile("mma.sync.aligned.m16n8k8.row.col.f32.tf32.tf32.f32 "
        "{%0,%1,%2,%3}, {%4,%5,%6,%7}, {%8,%9}, {%0,%1,%2,%3};"
        : "+f"(c[0]), "+f"(c[1]), "+f"(c[2]), "+f"(c[3])
        : "r"(a[0]), "r"(a[1]), "r"(a[2]), "r"(a[3]), "r"(b0), "r"(b1));
}

// =============================================================================
__global__ void init_kernel() {
    int k = threadIdx.x;
    g_counts[k] = 0;
    if (k == 0) { g_sum = 0.0; g_nflag = 0; }
}

// build Bcat1 = [Wf1 | Wx1], biascat1 = [bf1 | bx1]
__global__ void bcat1_kernel(const float* __restrict__ Wf1, const float* __restrict__ Wx1,
                             const float* __restrict__ bf1, const float* __restrict__ bx1) {
    int i = blockIdx.x * 256 + threadIdx.x;     // 0 .. 128*1024-1
    int k = i >> 10;
    int c = i & 1023;
    g_Bcat1[i] = (c < 512) ? Wf1[k * 512 + c] : Wx1[k * 512 + (c - 512)];
    if (i < 1024) g_biascat1[i] = (i < 512) ? bf1[i] : bx1[i - 512];
}

// transpose Wf2 [512,6240] -> Wf2T [6240,512] and Bcat[:,512:1024]
__global__ void transpose_kernel(const float* __restrict__ Wf2) {
    __shared__ float t[32][33];
    int bx = blockIdx.x * 32;   // d
    int by = blockIdx.y * 32;   // i
    int x0 = bx + threadIdx.x;
    #pragma unroll
    for (int r = 0; r < 32; r += 8) {
        int y = by + threadIdx.y + r;
        t[threadIdx.y + r][threadIdx.x] = Wf2[(size_t)y * EMBED_D + x0];
    }
    __syncthreads();
    int xo = by + threadIdx.x;
    #pragma unroll
    for (int r = 0; r < 32; r += 8) {
        int yo = bx + threadIdx.y + r;
        float v = t[threadIdx.x][threadIdx.y + r];
        g_Wf2T[(size_t)yo * CH + xo] = v;
        g_Bcat[(size_t)yo * 1024 + 512 + xo] = v;
    }
}

__global__ void copy_embed_kernel(const float* __restrict__ embed) {
    int i = blockIdx.x * 256 + threadIdx.x;
    float4 v = reinterpret_cast<const float4*>(embed)[i];
    int d = i >> 7;
    int c = (i & 127);
    reinterpret_cast<float4*>(&g_Bcat[(size_t)d * 1024])[c] = v;
}

// chunked fp64 partials for c[k], e2[k]
__global__ void vq_partial_kernel(const float* __restrict__ embed,
                                  const float* __restrict__ bf2) {
    int k = threadIdx.x;
    int d0 = blockIdx.x * DCHUNK;
    double cc = 0.0, ee = 0.0;
    for (int d = d0; d < d0 + DCHUNK; d++) {
        double e = (double)embed[(size_t)d * NUM_EMB + k];
        cc += (double)bf2[d] * e;
        ee += e * e;
    }
    g_pc [blockIdx.x * NUM_EMB + k] = cc;
    g_pe2[blockIdx.x * NUM_EMB + k] = ee;
}

__global__ void vq_reduce_kernel() {
    int k = threadIdx.x;
    double cc = 0.0, ee = 0.0;
    for (int s = 0; s < NCHUNKD; s++) {
        cc += g_pc [s * NUM_EMB + k];
        ee += g_pe2[s * NUM_EMB + k];
    }
    g_bias2[k] = (float)cc;
    g_cd[k]  = cc;
    g_e2[k]  = (float)ee;
    g_e2d[k] = ee;
}

__global__ void g_partial_kernel(const float* __restrict__ bf2) {
    int i = threadIdx.x;
    int d0 = blockIdx.x * DCHUNK;
    double s = 0.0;
    for (int d = d0; d < d0 + DCHUNK; d++)
        s += (double)g_Wf2T[(size_t)d * CH + i] * (double)bf2[d];
    g_pg[blockIdx.x * CH + i] = s;
}

__global__ void g_reduce_kernel() {
    int i = threadIdx.x;
    double s = 0.0;
    for (int c = 0; c < NCHUNKD; c++) s += g_pg[c * CH + i];
    g_bias2[CH + i] = (float)(2.0 * s);
}

__global__ void beta_kernel(const float* __restrict__ bf2) {
    __shared__ double red[256];
    double s = 0.0;
    for (int d = threadIdx.x; d < EMBED_D; d += 256) { double v = bf2[d]; s += v * v; }
    red[threadIdx.x] = s;
    __syncthreads();
    for (int t = 128; t; t >>= 1) {
        if (threadIdx.x < t) red[threadIdx.x] += red[threadIdx.x + t];
        __syncthreads();
    }
    if (threadIdx.x == 0) g_beta = (float)red[0];
}

// ---------------- SGEMM (SIMT fp32): BK=16, double-buffered ------------------
#define BM 128
#define BN 128
#define BK 16
template<bool HASBIAS, bool RELU, bool NGUARD, bool SPLITK>
__global__ void __launch_bounds__(256, 2)
sgemm2(const float* __restrict__ A, const float* __restrict__ B,
       const float* __restrict__ bias, float* __restrict__ C,
       int M, int N, int K, int lda, int ldb, int ldc) {
    __shared__ float As[2][BK][BM];
    __shared__ float Bs[2][BK][BN];
    const int tid = threadIdx.x;
    const int m0 = blockIdx.y * BM;
    const int n0 = blockIdx.x * BN;

    if (SPLITK) {
        int ko = blockIdx.z * KCHUNK;
        A += ko;
        B += (size_t)ko * ldb;
        C += (size_t)blockIdx.z * M * N;
        K = KCHUNK;
    }

    const int tm = (tid / 16) * 8;
    const int tn = (tid % 16) * 8;
    const int am = tid >> 1;
    const int ak = (tid & 1) * 8;

    float acc[8][8];
    #pragma unroll
    for (int i = 0; i < 8; i++)
        #pragma unroll
        for (int j = 0; j < 8; j++) acc[i][j] = 0.f;

    float4 pa0, pa1, pb0, pb1;
    float  pbs[8];
    const int bf0 = tid;
    const int bf1 = tid + 256;
    const int bk0 = bf0 >> 5, bn0c = (bf0 & 31) * 4;
    const int bk1 = bf1 >> 5, bn1c = (bf1 & 31) * 4;

    {
        pa0 = *reinterpret_cast<const float4*>(&A[(size_t)(m0 + am) * lda + ak]);
        pa1 = *reinterpret_cast<const float4*>(&A[(size_t)(m0 + am) * lda + ak + 4]);
        if (!NGUARD) {
            pb0 = *reinterpret_cast<const float4*>(&B[(size_t)bk0 * ldb + n0 + bn0c]);
            pb1 = *reinterpret_cast<const float4*>(&B[(size_t)bk1 * ldb + n0 + bn1c]);
        } else {
            #pragma unroll
            for (int t = 0; t < 4; t++) {
                int gn0 = n0 + bn0c + t, gn1 = n0 + bn1c + t;
                pbs[t]     = (gn0 < N) ? B[(size_t)bk0 * ldb + gn0] : 0.f;
                pbs[t + 4] = (gn1 < N) ? B[(size_t)bk1 * ldb + gn1] : 0.f;
            }
        }
    }
    As[0][ak + 0][am] = pa0.x; As[0][ak + 1][am] = pa0.y;
    As[0][ak + 2][am] = pa0.z; As[0][ak + 3][am] = pa0.w;
    As[0][ak + 4][am] = pa1.x; As[0][ak + 5][am] = pa1.y;
    As[0][ak + 6][am] = pa1.z; As[0][ak + 7][am] = pa1.w;
    if (!NGUARD) {
        *reinterpret_cast<float4*>(&Bs[0][bk0][bn0c]) = pb0;
        *reinterpret_cast<float4*>(&Bs[0][bk1][bn1c]) = pb1;
    } else {
        #pragma unroll
        for (int t = 0; t < 4; t++) {
            Bs[0][bk0][bn0c + t] = pbs[t];
            Bs[0][bk1][bn1c + t] = pbs[t + 4];
        }
    }
    __syncthreads();

    int buf = 0;
    for (int k0 = 0; k0 < K; k0 += BK) {
        bool more = (k0 + BK) < K;
        if (more) {
            int kn = k0 + BK;
            pa0 = *reinterpret_cast<const float4*>(&A[(size_t)(m0 + am) * lda + kn + ak]);
            pa1 = *reinterpret_cast<const float4*>(&A[(size_t)(m0 + am) * lda + kn + ak + 4]);
            if (!NGUARD) {
                pb0 = *reinterpret_cast<const float4*>(&B[(size_t)(kn + bk0) * ldb + n0 + bn0c]);
                pb1 = *reinterpret_cast<const float4*>(&B[(size_t)(kn + bk1) * ldb + n0 + bn1c]);
            } else {
                #pragma unroll
                for (int t = 0; t < 4; t++) {
                    int gn0 = n0 + bn0c + t, gn1 = n0 + bn1c + t;
                    pbs[t]     = (gn0 < N) ? B[(size_t)(kn + bk0) * ldb + gn0] : 0.f;
                    pbs[t + 4] = (gn1 < N) ? B[(size_t)(kn + bk1) * ldb + gn1] : 0.f;
                }
            }
        }
        #pragma unroll
        for (int kk = 0; kk < BK; kk++) {
            float ar[8], br[8];
            float4 a0 = *reinterpret_cast<const float4*>(&As[buf][kk][tm]);
            float4 a1 = *reinterpret_cast<const float4*>(&As[buf][kk][tm + 4]);
            ar[0]=a0.x; ar[1]=a0.y; ar[2]=a0.z; ar[3]=a0.w;
            ar[4]=a1.x; ar[5]=a1.y; ar[6]=a1.z; ar[7]=a1.w;
            float4 b0 = *reinterpret_cast<const float4*>(&Bs[buf][kk][tn]);
            float4 b1 = *reinterpret_cast<const float4*>(&Bs[buf][kk][tn + 4]);
            br[0]=b0.x; br[1]=b0.y; br[2]=b0.z; br[3]=b0.w;
            br[4]=b1.x; br[5]=b1.y; br[6]=b1.z; br[7]=b1.w;
            #pragma unroll
            for (int i = 0; i < 8; i++)
                #pragma unroll
                for (int j = 0; j < 8; j++)
                    acc[i][j] += ar[i] * br[j];
        }
        if (more) {
            int nb = buf ^ 1;
            As[nb][ak + 0][am] = pa0.x; As[nb][ak + 1][am] = pa0.y;
            As[nb][ak + 2][am] = pa0.z; As[nb][ak + 3][am] = pa0.w;
            As[nb][ak + 4][am] = pa1.x; As[nb][ak + 5][am] = pa1.y;
            As[nb][ak + 6][am] = pa1.z; As[nb][ak + 7][am] = pa1.w;
            if (!NGUARD) {
                *reinterpret_cast<float4*>(&Bs[nb][bk0][bn0c]) = pb0;
                *reinterpret_cast<float4*>(&Bs[nb][bk1][bn1c]) = pb1;
            } else {
                #pragma unroll
                for (int t = 0; t < 4; t++) {
                    Bs[nb][bk0][bn0c + t] = pbs[t];
                    Bs[nb][bk1][bn1c + t] = pbs[t + 4];
                }
            }
            __syncthreads();
            buf = nb;
        }
    }

    #pragma unroll
    for (int i = 0; i < 8; i++) {
        int gm = m0 + tm + i;
        #pragma unroll
        for (int j = 0; j < 8; j++) {
            int gn = n0 + tn + j;
            if (!NGUARD || gn < N) {
                float v = acc[i][j];
                if (HASBIAS) v += bias[gn];
                if (RELU)    v = fmaxf(v, 0.f);
                C[(size_t)gm * ldc + gn] = v;
            }
        }
    }
}

// ---------- reduce split-K partials and transpose -> g_MGT [1024][512] -------
__global__ void mgt_reduce_kernel() {
    __shared__ float t[32][33];
    int n0 = blockIdx.x * 32;   // over 1024
    int k0 = blockIdx.y * 32;   // over 512
    int n = n0 + threadIdx.x;
    #pragma unroll
    for (int r = 0; r < 32; r += 8) {
        int k = k0 + threadIdx.y + r;
        float s = 0.f;
        #pragma unroll
        for (int p = 0; p < NSPLIT; p++)
            s += g_part[(size_t)p * (CH * 1024) + (size_t)k * 1024 + n];
        t[threadIdx.y + r][threadIdx.x] = s;
    }
    __syncthreads();
    int k = k0 + threadIdx.x;
    #pragma unroll
    for (int r = 0; r < 32; r += 8) {
        int n2 = n0 + threadIdx.y + r;
        g_MGT[(size_t)n2 * CH + k] = t[threadIdx.x][threadIdx.y + r];
    }
}

// =================== mma.sync tf32 GEMM: SU = h1 @ MGT^T + bias ==============
// A = h1cat [16384,1024] cols [0,512); Bt = MGT [1024][512]; C = SU [16384,1024]
// Block tile 128x128xK16, 8 warps each 32x64 (m16n8k8 fragments).
#define AS_STR 136
#define BS_STR 20
__global__ void __launch_bounds__(256, 2)
su_hmma_kernel(const float* __restrict__ A, const float* __restrict__ Bt,
               const float* __restrict__ bias, float* __restrict__ C) {
    __shared__ __align__(16) uint32_t As[2][16][AS_STR];
    __shared__ __align__(16) uint32_t Bs[2][128][BS_STR];
    const int tid  = threadIdx.x;
    const int lane = tid & 31;
    const int wid  = tid >> 5;
    const int m0 = blockIdx.y * 128;
    const int n0 = blockIdx.x * 128;
    const int wm = (wid & 3) * 32;
    const int wn = (wid >> 2) * 64;
    const int lq = lane >> 2;     // 0..7
    const int lr = lane & 3;      // 0..3

    float acc[2][8][4];
    #pragma unroll
    for (int mi = 0; mi < 2; mi++)
        #pragma unroll
        for (int ni = 0; ni < 8; ni++)
            #pragma unroll
            for (int j = 0; j < 4; j++) acc[mi][ni][j] = 0.f;

    const int am = tid >> 1;          // A row 0..127
    const int ak = (tid & 1) * 8;     // A col base 0/8
    const int brow = tid >> 2;        // B row 0..63 (i=0), +64 (i=1)
    const int bc4 = (tid & 3) * 4;    // B col base in floats

    float4 pa0, pa1, pb0, pb1;

    // prime k0 = 0
    pa0 = *reinterpret_cast<const float4*>(&A[(size_t)(m0 + am) * 1024 + ak]);
    pa1 = *reinterpret_cast<const float4*>(&A[(size_t)(m0 + am) * 1024 + ak + 4]);
    pb0 = *reinterpret_cast<const float4*>(&Bt[(size_t)(n0 + brow) * 512 + bc4]);
    pb1 = *reinterpret_cast<const float4*>(&Bt[(size_t)(n0 + brow + 64) * 512 + bc4]);
    {
        As[0][ak + 0][am] = f2tf32(pa0.x); As[0][ak + 1][am] = f2tf32(pa0.y);
        As[0][ak + 2][am] = f2tf32(pa0.z); As[0][ak + 3][am] = f2tf32(pa0.w);
        As[0][ak + 4][am] = f2tf32(pa1.x); As[0][ak + 5][am] = f2tf32(pa1.y);
        As[0][ak + 6][am] = f2tf32(pa1.z); As[0][ak + 7][am] = f2tf32(pa1.w);
        uint4 u0 = { f2tf32(pb0.x), f2tf32(pb0.y), f2tf32(pb0.z), f2tf32(pb0.w) };
        uint4 u1 = { f2tf32(pb1.x), f2tf32(pb1.y), f2tf32(pb1.z), f2tf32(pb1.w) };
        *reinterpret_cast<uint4*>(&Bs[0][brow][bc4])      = u0;
        *reinterpret_cast<uint4*>(&Bs[0][brow + 64][bc4]) = u1;
    }
    __syncthreads();

    int buf = 0;
    for (int k0 = 0; k0 < 512; k0 += 16) {
        bool more = (k0 + 16) < 512;
        if (more) {
            int kn = k0 + 16;
            pa0 = *reinterpret_cast<const float4*>(&A[(size_t)(m0 + am) * 1024 + kn + ak]);
            pa1 = *reinterpret_cast<const float4*>(&A[(size_t)(m0 + am) * 1024 + kn + ak + 4]);
            pb0 = *reinterpret_cast<const float4*>(&Bt[(size_t)(n0 + brow) * 512 + kn + bc4]);
            pb1 = *reinterpret_cast<const float4*>(&Bt[(size_t)(n0 + brow + 64) * 512 + kn + bc4]);
        }
        #pragma unroll
        for (int kh = 0; kh < 2; kh++) {
            const int kk = kh * 8;
            uint32_t af[2][4];
            #pragma unroll
            for (int mi = 0; mi < 2; mi++) {
                int mb = wm + mi * 16 + lq;
                af[mi][0] = As[buf][kk + lr][mb];
                af[mi][1] = As[buf][kk + lr][mb + 8];
                af[mi][2] = As[buf][kk + 4 + lr][mb];
                af[mi][3] = As[buf][kk + 4 + lr][mb + 8];
            }
            #pragma unroll
            for (int ni = 0; ni < 8; ni++) {
                int nb = wn + ni * 8 + lq;
                uint32_t b0 = Bs[buf][nb][kk + lr];
                uint32_t b1 = Bs[buf][nb][kk + 4 + lr];
                mma8(acc[0][ni], af[0], b0, b1);
                mma8(acc[1][ni], af[1], b0, b1);
            }
        }
        if (more) {
            int nb = buf ^ 1;
            As[nb][ak + 0][am] = f2tf32(pa0.x); As[nb][ak + 1][am] = f2tf32(pa0.y);
            As[nb][ak + 2][am] = f2tf32(pa0.z); As[nb][ak + 3][am] = f2tf32(pa0.w);
            As[nb][ak + 4][am] = f2tf32(pa1.x); As[nb][ak + 5][am] = f2tf32(pa1.y);
            As[nb][ak + 6][am] = f2tf32(pa1.z); As[nb][ak + 7][am] = f2tf32(pa1.w);
            uint4 u0 = { f2tf32(pb0.x), f2tf32(pb0.y), f2tf32(pb0.z), f2tf32(pb0.w) };
            uint4 u1 = { f2tf32(pb1.x), f2tf32(pb1.y), f2tf32(pb1.z), f2tf32(pb1.w) };
            *reinterpret_cast<uint4*>(&Bs[nb][brow][bc4])      = u0;
            *reinterpret_cast<uint4*>(&Bs[nb][brow + 64][bc4]) = u1;
            __syncthreads();
            buf = nb;
        }
    }

    // epilogue
    #pragma unroll
    for (int mi = 0; mi < 2; mi++) {
        int r0 = m0 + wm + mi * 16 + lq;
        #pragma unroll
        for (int ni = 0; ni < 8; ni++) {
            int c = n0 + wn + ni * 8 + lr * 2;
            float bv0 = bias[c], bv1 = bias[c + 1];
            float2 v0 = { acc[mi][ni][0] + bv0, acc[mi][ni][1] + bv1 };
            float2 v1 = { acc[mi][ni][2] + bv0, acc[mi][ni][3] + bv1 };
            *reinterpret_cast<float2*>(&C[(size_t)r0 * 1024 + c]) = v0;
            *reinterpret_cast<float2*>(&C[(size_t)(r0 + 8) * 1024 + c]) = v1;
        }
    }
}

// ---------- per-row top-2 argmin + flag near-ties + diff accumulation --------
__global__ void argmin_kernel(float* __restrict__ out_ind_f) {
    __shared__ double s_q[8];
    int warp = threadIdx.x >> 5;
    int lane = threadIdx.x & 31;
    int b = blockIdx.x * 8 + warp;

    const float* su = g_SU + (size_t)b * 1024;
    const float* h  = g_h1cat + (size_t)b * 1024;

    float q = 0.f;
    #pragma unroll 4
    for (int j = lane; j < CH; j += 32)
        q += su[512 + j] * h[j];
    #pragma unroll
    for (int o = 16; o; o >>= 1) q += __shfl_xor_sync(0xFFFFFFFFu, q, o);

    float v1 = FLT_MAX, v2 = FLT_MAX;
    int   k1 = -1, k2 = -1;
    for (int k = lane; k < NUM_EMB; k += 32) {
        float v = g_e2[k] - 2.f * su[k];
        if (v < v1 || (v == v1 && k < k1)) { v2 = v1; k2 = k1; v1 = v; k1 = k; }
        else if (v < v2 || (v == v2 && k < k2)) { v2 = v; k2 = k; }
    }
    #pragma unroll
    for (int o = 16; o; o >>= 1) {
        float ov1 = __shfl_xor_sync(0xFFFFFFFFu, v1, o);
        int   ok1 = __shfl_xor_sync(0xFFFFFFFFu, k1, o);
        float ov2 = __shfl_xor_sync(0xFFFFFFFFu, v2, o);
        int   ok2 = __shfl_xor_sync(0xFFFFFFFFu, k2, o);
        if (!(ov1 == v1 && ok1 == k1)) {
            if (ov1 < v1 || (ov1 == v1 && ok1 < k1)) { v2 = v1; k2 = k1; v1 = ov1; k1 = ok1; }
            else if (ov1 < v2 || (ov1 == v2 && ok1 < k2)) { v2 = ov1; k2 = ok1; }
        }
        if (!(ov2 == v1 && ok2 == k1)) {
            if (ov2 < v1 || (ov2 == v1 && ok2 < k1)) { v2 = v1; k2 = k1; v1 = ov2; k1 = ok2; }
            else if (ov2 < v2 || (ov2 == v2 && ok2 < k2)) { v2 = ov2; k2 = ok2; }
        }
    }
    if (lane == 0) {
        g_ind[b] = k1;
        out_ind_f[b] = (float)k1;
        s_q[warp] = (double)(q + g_beta + v1);
        if (v2 - v1 < MARGIN && k2 >= 0) {
            int idx = atomicAdd(&g_nflag, 1);
            if (idx < MAXFLAG) {
                g_fb[idx] = b; g_fk1[idx] = k1; g_fk2[idx] = k2;
            }
        }
    }
    __syncthreads();
    if (threadIdx.x == 0) {
        double t = 0.0;
        #pragma unroll
        for (int i = 0; i < 8; i++) t += s_q[i];
        atomicAdd(&g_sum, t);
    }
}

// ----- refinement via M (fp64): one warp per flagged row -----
__global__ void refine_kernel(float* __restrict__ out_ind_f) {
    int nf = g_nflag; if (nf > MAXFLAG) nf = MAXFLAG;
    int f = (blockIdx.x * 256 + threadIdx.x) >> 5;
    int lane = threadIdx.x & 31;
    if (f >= nf) return;
    int b = g_fb[f];
    int k1 = g_fk1[f], k2 = g_fk2[f];
    const float* h  = g_h1cat + (size_t)b * 1024;
    const float* m1 = g_MGT + (size_t)k1 * CH;
    const float* m2 = g_MGT + (size_t)k2 * CH;
    double s = 0.0;
    #pragma unroll 4
    for (int j = lane; j < CH; j += 32)
        s += (double)h[j] * ((double)m2[j] - (double)m1[j]);
    #pragma unroll
    for (int o = 16; o; o >>= 1) s += __shfl_xor_sync(0xFFFFFFFFu, s, o);
    if (lane == 0) {
        double delta = (g_e2d[k2] - g_e2d[k1]) - 2.0 * (s + (g_cd[k2] - g_cd[k1]));
        if (delta < 0.0 || (delta == 0.0 && k2 < k1)) {
            g_ind[b] = k2;
            out_ind_f[b] = (float)k2;
        }
    }
}

// ---------------- counts (post-refinement) ----------------
__global__ void count_kernel() {
    __shared__ int hist[NUM_EMB];
    for (int i = threadIdx.x; i < NUM_EMB; i += 256) hist[i] = 0;
    __syncthreads();
    int i0 = blockIdx.x * 2048;
    for (int i = threadIdx.x; i < 2048; i += 256)
        atomicAdd(&hist[g_ind[i0 + i]], 1);
    __syncthreads();
    for (int i = threadIdx.x; i < NUM_EMB; i += 256)
        if (hist[i]) atomicAdd(&g_counts[i], hist[i]);
}

// ---------------- per-sample expert MLP decode ----------------
__global__ void decoder_kernel(const float* __restrict__ W1, const float* __restrict__ b1,
                               const float* __restrict__ W2, const float* __restrict__ b2,
                               float* __restrict__ out) {
    __shared__ float exs[8][64];
    __shared__ float hs [8][64];
    int warp = threadIdx.x >> 5;
    int lane = threadIdx.x & 31;
    int b = blockIdx.x * 8 + warp;

    exs[warp][lane]      = g_ex[(size_t)b * 64 + lane];
    exs[warp][lane + 32] = g_ex[(size_t)b * 64 + lane + 32];
    __syncwarp();

    int k = g_ind[b];
    const float* w1 = W1 + (size_t)k * 64 * 64;
    float h0 = b1[k * 64 + lane];
    float h1 = b1[k * 64 + lane + 32];
    #pragma unroll 8
    for (int i = 0; i < 64; i++) {
        float xi = exs[warp][i];
        h0 += xi * w1[i * 64 + lane];
        h1 += xi * w1[i * 64 + lane + 32];
    }
    hs[warp][lane]      = fmaxf(h0, 0.f);
    hs[warp][lane + 32] = fmaxf(h1, 0.f);
    __syncwarp();

    const float* w2 = W2 + (size_t)k * 64 * 32;
    float o = b2[k * 32 + lane];
    #pragma unroll 8
    for (int i = 0; i < 64; i++)
        o += hs[warp][i] * w2[i * 32 + lane];
    out[(size_t)b * 32 + lane] = o;
}

// ---------------- finalize scalars ----------------
__global__ void finalize_kernel(float* __restrict__ out) {
    __shared__ float red[512];
    int k = threadIdx.x;
    float p = (float)g_counts[k] / (float)BATCH;
    red[k] = -p * logf(p + 1e-10f);
    __syncthreads();
    for (int s = 256; s; s >>= 1) {
        if (k < s) red[k] += red[k + s];
        __syncthreads();
    }
    if (k == 0) {
        out[OUT_DIFF] = (float)(g_sum / ((double)BATCH * (double)EMBED_D));
        out[OUT_PERP] = expf(red[0]);
    }
}

// ---------------- launch ----------------
extern "C" void kernel_launch(void* const* d_in, const int* in_sizes, int n_in,
                              void* d_out, int out_size) {
    const float* x     = (const float*)d_in[0];
    const float* Wf1   = (const float*)d_in[1];
    const float* bf1   = (const float*)d_in[2];
    const float* Wf2   = (const float*)d_in[3];
    const float* bf2   = (const float*)d_in[4];
    const float* Wx1   = (const float*)d_in[5];
    const float* bx1   = (const float*)d_in[6];
    const float* Wx2   = (const float*)d_in[7];
    const float* bx2   = (const float*)d_in[8];
    const float* embed = (const float*)d_in[9];
    const float* W1    = (const float*)d_in[10];
    const float* b1    = (const float*)d_in[11];
    const float* W2    = (const float*)d_in[12];
    const float* b2    = (const float*)d_in[13];
    float* out = (float*)d_out;

    float *p_h1cat, *p_SU, *p_ex, *p_MGT, *p_bias2, *p_part, *p_Bcat, *p_Bcat1, *p_biascat1;
    cudaGetSymbolAddress((void**)&p_h1cat, g_h1cat);
    cudaGetSymbolAddress((void**)&p_SU,    g_SU);
    cudaGetSymbolAddress((void**)&p_ex,    g_ex);
    cudaGetSymbolAddress((void**)&p_MGT,   g_MGT);
    cudaGetSymbolAddress((void**)&p_bias2, g_bias2);
    cudaGetSymbolAddress((void**)&p_part,  g_part);
    cudaGetSymbolAddress((void**)&p_Bcat,  g_Bcat);
    cudaGetSymbolAddress((void**)&p_Bcat1, g_Bcat1);
    cudaGetSymbolAddress((void**)&p_biascat1, g_biascat1);

    init_kernel<<<1, 512>>>();
    bcat1_kernel<<<IN_C * 1024 / 256, 256>>>(Wf1, Wx1, bf1, bx1);
    transpose_kernel<<<dim3(EMBED_D / 32, CH / 32), dim3(32, 8)>>>(Wf2);
    copy_embed_kernel<<<EMBED_D * NUM_EMB / 4 / 256, 256>>>(embed);
    vq_partial_kernel<<<NCHUNKD, 512>>>(embed, bf2);
    g_partial_kernel<<<NCHUNKD, 512>>>(bf2);
    vq_reduce_kernel<<<1, 512>>>();
    g_reduce_kernel<<<1, 512>>>();
    beta_kernel<<<1, 256>>>(bf2);

    // [M|G] = Wf2 @ [embed | Wf2^T]  (split-K fp32) -> partials -> MGT (transposed)
    sgemm2<false, false, false, true><<<dim3(8, 4, NSPLIT), 256>>>(
        Wf2, p_Bcat, nullptr, p_part, CH, 1024, EMBED_D, EMBED_D, 1024, 1024);
    mgt_reduce_kernel<<<dim3(32, 16), dim3(32, 8)>>>();

    // h1cat = relu(x @ [Wf1|Wx1] + [bf1|bx1])
    sgemm2<true, true, false, false><<<dim3(8, 128), 256>>>(
        x, p_Bcat1, p_biascat1, p_h1cat, BATCH, 1024, IN_C, IN_C, 1024, 1024);

    // SU = h1 @ [M|G] + [c|2g]   (mma.sync tf32)
    su_hmma_kernel<<<dim3(8, 128), 256>>>(p_h1cat, p_MGT, p_bias2, p_SU);

    // ex = h1x @ Wx2 + bx2
    sgemm2<true, false, true, false><<<dim3(1, 128), 256>>>(
        p_h1cat + 512, Wx2, bx2, p_ex, BATCH, DEC_IN, CH, 1024, DEC_IN, DEC_IN);

    // top-2 argmin + near-tie flagging
    argmin_kernel<<<BATCH / 8, 256>>>(out + OUT_IND);

    // exact fp64 refinement through M (one warp per flag)
    refine_kernel<<<MAXFLAG / 8, 256>>>(out + OUT_IND);

    // counts after refinement
    count_kernel<<<BATCH / 2048, 256>>>();

    // expert decoder -> dec
    decoder_kernel<<<BATCH / 8, 256>>>(W1, b1, W2, b2, out);

    // diff + perplexity
    finalize_kernel<<<1, 512>>>(out);
}

// round 6
// speedup vs baseline: 9.1402x; 1.1599x over previous
#include <cuda_runtime.h>
#include <cuda_bf16.h>
#include <math.h>
#include <float.h>
#include <stdint.h>

// Problem dims
#define BATCH    16384
#define IN_C     128
#define CH       512
#define EMBED_D  6240
#define NUM_EMB  512
#define DEC_IN   64
#define DATA_Y   32

// Output layout (float32): dec[B*32], diff[1], embed_ind[B], perplexity[1]
#define OUT_DIFF  (BATCH * DATA_Y)
#define OUT_IND   (OUT_DIFF + 1)
#define OUT_PERP  (OUT_IND + BATCH)

#define MAXFLAG 16384
#define MARGIN  2.0f

#define NSPLIT  26
#define KCHUNK  240           // 26 * 240 = 6240  (MG GEMM split-K)
#define NCHUNKD 195
#define DCHUNK  32            // 195 * 32 = 6240  (vq fp64 prep chunks)
#define NCHUNKG 5
#define GCHUNK  1248          // 5 * 1248 = 6240  (g fp64 chunks)

// ---------------- scratch (device globals) ----------------
__device__ float  g_h1cat[BATCH * 1024];        // [h1 | h1x]
__device__ float  g_SU [BATCH * 1024];          // [s | u]
__device__ float  g_ex [BATCH * DEC_IN];
__device__ float  g_part[NSPLIT * 1024 * CH];   // MGT split-K partials
__device__ float  g_MGT [1024 * CH];            // row n = column n of [M|G]
__device__ float  g_BcatT[1024 * EMBED_D];      // [embed^T ; Wf2]
__device__ float  g_Bcat1T[1024 * IN_C];        // [Wf1 | Wx1]^T
__device__ float  g_biascat1[1024];             // [bf1 | bx1]
__device__ float  g_bias2[1024];                // [c | 2g]
__device__ float  g_e2[NUM_EMB];
__device__ double g_e2d[NUM_EMB];
__device__ double g_cd[NUM_EMB];
__device__ float  g_beta;
__device__ int    g_counts[NUM_EMB];
__device__ double g_sum;
__device__ int    g_ind[BATCH];
__device__ double g_pc [NCHUNKD * NUM_EMB];
__device__ double g_pe2[NCHUNKD * NUM_EMB];
__device__ double g_pg [NCHUNKG * CH];
// refinement state
__device__ int    g_nflag;
__device__ int    g_fb [MAXFLAG];
__device__ int    g_fk1[MAXFLAG];
__device__ int    g_fk2[MAXFLAG];

__device__ __forceinline__ uint32_t f2tf32(float x) {
    uint32_t u;
    asm("cvt.rna.tf32.f32 %0, %1;" : "=r"(u) : "f"(x));
    return u;
}
__device__ __forceinline__ void mma8(float* c, const uint32_t* a,
                                     uint32_t b0, uint32_t b1) {
    asm volatile("mma.sync.aligned.m16n8k8.row.col.f32.tf32.tf32.f32 "
        "{%0,%1,%2,%3}, {%4,%5,%6,%7}, {%8,%9}, {%0,%1,%2,%3};"
        : "+f"(c[0]), "+f"(c[1]), "+f"(c[2]), "+f"(c[3])
        : "r"(a[0]), "r"(a[1]), "r"(a[2]), "r"(a[3]), "r"(b0), "r"(b1));
}

// =============================================================================
__global__ void init_kernel(const float* __restrict__ bf1,
                            const float* __restrict__ bx1) {
    int k = threadIdx.x;             // 0..1023
    if (k < NUM_EMB) g_counts[k] = 0;
    g_biascat1[k] = (k < 512) ? bf1[k] : bx1[k - 512];
    if (k == 0) { g_sum = 0.0; g_nflag = 0; }
}

// embed [6240][512] -> BcatT rows [0,512):  BcatT[k][d] = embed[d][k]
__global__ void embedT_kernel(const float* __restrict__ embed) {
    __shared__ float t[32][33];
    int d0 = blockIdx.x * 32;
    int k0 = blockIdx.y * 32;
    #pragma unroll
    for (int r = 0; r < 32; r += 8)
        t[threadIdx.y + r][threadIdx.x] =
            embed[(size_t)(d0 + threadIdx.y + r) * NUM_EMB + k0 + threadIdx.x];
    __syncthreads();
    #pragma unroll
    for (int r = 0; r < 32; r += 8)
        g_BcatT[(size_t)(k0 + threadIdx.y + r) * EMBED_D + d0 + threadIdx.x] =
            t[threadIdx.x][threadIdx.y + r];
}

// Wf2 [512][6240] copied into BcatT rows [512,1024)
__global__ void wf2copy_kernel(const float* __restrict__ Wf2) {
    size_t i = (size_t)blockIdx.x * 256 + threadIdx.x;   // float4 index
    reinterpret_cast<float4*>(g_BcatT + (size_t)512 * EMBED_D)[i] =
        reinterpret_cast<const float4*>(Wf2)[i];
}

// Bcat1T[n][k] = (n<512 ? Wf1[k][n] : Wx1[k][n-512]),  n over 1024, k over 128
__global__ void bcat1t_kernel(const float* __restrict__ Wf1,
                              const float* __restrict__ Wx1) {
    __shared__ float t[32][33];
    int n0 = blockIdx.x * 32;
    int k0 = blockIdx.y * 32;
    #pragma unroll
    for (int r = 0; r < 32; r += 8) {
        int k = k0 + threadIdx.y + r;
        int n = n0 + threadIdx.x;
        t[threadIdx.y + r][threadIdx.x] =
            (n < 512) ? Wf1[(size_t)k * 512 + n] : Wx1[(size_t)k * 512 + n - 512];
    }
    __syncthreads();
    #pragma unroll
    for (int r = 0; r < 32; r += 8)
        g_Bcat1T[(size_t)(n0 + threadIdx.y + r) * IN_C + k0 + threadIdx.x] =
            t[threadIdx.x][threadIdx.y + r];
}

// chunked fp64 partials for c[k], e2[k]  (coalesced along k)
__global__ void vq_partial_kernel(const float* __restrict__ embed,
                                  const float* __restrict__ bf2) {
    int k = threadIdx.x;
    int d0 = blockIdx.x * DCHUNK;
    double cc = 0.0, ee = 0.0;
    for (int d = d0; d < d0 + DCHUNK; d++) {
        double e = (double)embed[(size_t)d * NUM_EMB + k];
        cc += (double)bf2[d] * e;
        ee += e * e;
    }
    g_pc [blockIdx.x * NUM_EMB + k] = cc;
    g_pe2[blockIdx.x * NUM_EMB + k] = ee;
}

__global__ void vq_reduce_kernel() {
    int k = threadIdx.x;
    double cc = 0.0, ee = 0.0;
    for (int s = 0; s < NCHUNKD; s++) {
        cc += g_pc [s * NUM_EMB + k];
        ee += g_pe2[s * NUM_EMB + k];
    }
    g_bias2[k] = (float)cc;
    g_cd[k]  = cc;
    g_e2[k]  = (float)ee;
    g_e2d[k] = ee;
}

// g partials: warp per (row i, chunk c) directly on Wf2 (coalesced)
__global__ void g_partial_kernel(const float* __restrict__ Wf2,
                                 const float* __restrict__ bf2) {
    int gw = blockIdx.x * 8 + (threadIdx.x >> 5);   // 0 .. 512*NCHUNKG-1
    int lane = threadIdx.x & 31;
    int i = gw % CH;
    int c = gw / CH;
    const float* w = Wf2 + (size_t)i * EMBED_D + c * GCHUNK;
    const float* b = bf2 + c * GCHUNK;
    double s = 0.0;
    #pragma unroll 4
    for (int t = lane; t < GCHUNK; t += 32)
        s += (double)w[t] * (double)b[t];
    #pragma unroll
    for (int o = 16; o; o >>= 1) s += __shfl_xor_sync(0xFFFFFFFFu, s, o);
    if (lane == 0) g_pg[c * CH + i] = s;
}

__global__ void g_reduce_kernel() {
    int i = threadIdx.x;
    double s = 0.0;
    #pragma unroll
    for (int c = 0; c < NCHUNKG; c++) s += g_pg[c * CH + i];
    g_bias2[CH + i] = (float)(2.0 * s);
}

__global__ void beta_kernel(const float* __restrict__ bf2) {
    __shared__ double red[256];
    double s = 0.0;
    for (int d = threadIdx.x; d < EMBED_D; d += 256) { double v = bf2[d]; s += v * v; }
    red[threadIdx.x] = s;
    __syncthreads();
    for (int t = 128; t; t >>= 1) {
        if (threadIdx.x < t) red[threadIdx.x] += red[threadIdx.x + t];
        __syncthreads();
    }
    if (threadIdx.x == 0) g_beta = (float)red[0];
}

// =============== 3xTF32 HMMA GEMM: C = op(A @ Bt^T [+bias][relu]) ============
// A row-major [M, lda] (K contiguous); Bt row-major [N, ldb] (= B col-major).
// Block tile 128x128, BK=16 double-buffered, 8 warps each 32x64.
// acc += Ahi*Bhi + Ahi*Blo + Alo*Bhi   (fp32-grade accuracy)
#define X3_SMEM_BYTES 75776
// u32 offsets inside dynamic smem
#define AHI_OFF 0
#define ALO_OFF 4352
#define BHI_OFF 8704
#define BLO_OFF 13824

template<bool HASBIAS, bool RELU, bool SPLITK>
__global__ void __launch_bounds__(256)
hmma_x3(const float* __restrict__ A, const float* __restrict__ Bt,
        const float* __restrict__ bias, float* __restrict__ C,
        int M, int N, int K, int lda, int ldb, int ldc) {
    extern __shared__ uint32_t sm[];
    const int tid  = threadIdx.x;
    const int lane = tid & 31;
    const int wid  = tid >> 5;
    const int n0 = blockIdx.x * 128;
    const int m0 = blockIdx.y * 128;
    if (SPLITK) {
        A  += blockIdx.z * KCHUNK;
        Bt += blockIdx.z * KCHUNK;
        C  += (size_t)blockIdx.z * M * N;
        K = KCHUNK;
    }
    const int wm = (wid & 3) * 32;
    const int wn = (wid >> 2) * 64;
    const int lq = lane >> 2;
    const int lr = lane & 3;

    float acc[2][8][4];
    #pragma unroll
    for (int mi = 0; mi < 2; mi++)
        #pragma unroll
        for (int ni = 0; ni < 8; ni++)
            #pragma unroll
            for (int j = 0; j < 4; j++) acc[mi][ni][j] = 0.f;

    const int ar  = tid >> 2;        // row 0..63, +64 on second iter
    const int ac4 = (tid & 3) * 4;   // k offset within chunk

    float4 pa[2], pb[2];

    // prime chunk 0
    #pragma unroll
    for (int i = 0; i < 2; i++) {
        pa[i] = *reinterpret_cast<const float4*>(&A [(size_t)(m0 + ar + 64 * i) * lda + ac4]);
        pb[i] = *reinterpret_cast<const float4*>(&Bt[(size_t)(n0 + ar + 64 * i) * ldb + ac4]);
    }
    {
        #pragma unroll
        for (int i = 0; i < 2; i++) {
            int row = ar + 64 * i;
            const float* av = reinterpret_cast<const float*>(&pa[i]);
            #pragma unroll
            for (int j = 0; j < 4; j++) {
                uint32_t hi = f2tf32(av[j]);
                float lo = av[j] - __uint_as_float(hi);
                sm[AHI_OFF + (ac4 + j) * 136 + row] = hi;
                sm[ALO_OFF + (ac4 + j) * 136 + row] = f2tf32(lo);
            }
            const float* bv = reinterpret_cast<const float*>(&pb[i]);
            uint4 uh, ul;
            uh.x = f2tf32(bv[0]); ul.x = f2tf32(bv[0] - __uint_as_float(uh.x));
            uh.y = f2tf32(bv[1]); ul.y = f2tf32(bv[1] - __uint_as_float(uh.y));
            uh.z = f2tf32(bv[2]); ul.z = f2tf32(bv[2] - __uint_as_float(uh.z));
            uh.w = f2tf32(bv[3]); ul.w = f2tf32(bv[3] - __uint_as_float(uh.w));
            *reinterpret_cast<uint4*>(&sm[BHI_OFF + row * 20 + ac4]) = uh;
            *reinterpret_cast<uint4*>(&sm[BLO_OFF + row * 20 + ac4]) = ul;
        }
    }
    __syncthreads();

    int buf = 0;
    for (int k0 = 0; k0 < K; k0 += 16) {
        bool more = (k0 + 16) < K;
        if (more) {
            int kn = k0 + 16;
            #pragma unroll
            for (int i = 0; i < 2; i++) {
                pa[i] = *reinterpret_cast<const float4*>(&A [(size_t)(m0 + ar + 64 * i) * lda + kn + ac4]);
                pb[i] = *reinterpret_cast<const float4*>(&Bt[(size_t)(n0 + ar + 64 * i) * ldb + kn + ac4]);
            }
        }
        const int ab = buf * 2176;
        const int bb = buf * 2560;
        #pragma unroll
        for (int kh = 0; kh < 2; kh++) {
            const int kk = kh * 8;
            uint32_t ah[2][4], al[2][4];
            #pragma unroll
            for (int mi = 0; mi < 2; mi++) {
                int mb = wm + mi * 16 + lq;
                ah[mi][0] = sm[AHI_OFF + ab + (kk + lr) * 136 + mb];
                ah[mi][1] = sm[AHI_OFF + ab + (kk + lr) * 136 + mb + 8];
                ah[mi][2] = sm[AHI_OFF + ab + (kk + 4 + lr) * 136 + mb];
                ah[mi][3] = sm[AHI_OFF + ab + (kk + 4 + lr) * 136 + mb + 8];
                al[mi][0] = sm[ALO_OFF + ab + (kk + lr) * 136 + mb];
                al[mi][1] = sm[ALO_OFF + ab + (kk + lr) * 136 + mb + 8];
                al[mi][2] = sm[ALO_OFF + ab + (kk + 4 + lr) * 136 + mb];
                al[mi][3] = sm[ALO_OFF + ab + (kk + 4 + lr) * 136 + mb + 8];
            }
            #pragma unroll
            for (int ni = 0; ni < 8; ni++) {
                int nb = wn + ni * 8 + lq;
                uint32_t bh0 = sm[BHI_OFF + bb + nb * 20 + kk + lr];
                uint32_t bh1 = sm[BHI_OFF + bb + nb * 20 + kk + 4 + lr];
                uint32_t bl0 = sm[BLO_OFF + bb + nb * 20 + kk + lr];
                uint32_t bl1 = sm[BLO_OFF + bb + nb * 20 + kk + 4 + lr];
                mma8(acc[0][ni], ah[0], bh0, bh1);
                mma8(acc[0][ni], ah[0], bl0, bl1);
                mma8(acc[0][ni], al[0], bh0, bh1);
                mma8(acc[1][ni], ah[1], bh0, bh1);
                mma8(acc[1][ni], ah[1], bl0, bl1);
                mma8(acc[1][ni], al[1], bh0, bh1);
            }
        }
        if (more) {
            int nb = buf ^ 1;
            const int ab2 = nb * 2176;
            const int bb2 = nb * 2560;
            #pragma unroll
            for (int i = 0; i < 2; i++) {
                int row = ar + 64 * i;
                const float* av = reinterpret_cast<const float*>(&pa[i]);
                #pragma unroll
                for (int j = 0; j < 4; j++) {
                    uint32_t hi = f2tf32(av[j]);
                    float lo = av[j] - __uint_as_float(hi);
                    sm[AHI_OFF + ab2 + (ac4 + j) * 136 + row] = hi;
                    sm[ALO_OFF + ab2 + (ac4 + j) * 136 + row] = f2tf32(lo);
                }
                const float* bv = reinterpret_cast<const float*>(&pb[i]);
                uint4 uh, ul;
                uh.x = f2tf32(bv[0]); ul.x = f2tf32(bv[0] - __uint_as_float(uh.x));
                uh.y = f2tf32(bv[1]); ul.y = f2tf32(bv[1] - __uint_as_float(uh.y));
                uh.z = f2tf32(bv[2]); ul.z = f2tf32(bv[2] - __uint_as_float(uh.z));
                uh.w = f2tf32(bv[3]); ul.w = f2tf32(bv[3] - __uint_as_float(uh.w));
                *reinterpret_cast<uint4*>(&sm[BHI_OFF + bb2 + row * 20 + ac4]) = uh;
                *reinterpret_cast<uint4*>(&sm[BLO_OFF + bb2 + row * 20 + ac4]) = ul;
            }
            __syncthreads();
            buf = nb;
        }
    }

    // epilogue
    #pragma unroll
    for (int mi = 0; mi < 2; mi++) {
        int r0 = m0 + wm + mi * 16 + lq;
        #pragma unroll
        for (int ni = 0; ni < 8; ni++) {
            int c = n0 + wn + ni * 8 + lr * 2;
            float bv0 = HASBIAS ? bias[c] : 0.f;
            float bv1 = HASBIAS ? bias[c + 1] : 0.f;
            float2 v0 = { acc[mi][ni][0] + bv0, acc[mi][ni][1] + bv1 };
            float2 v1 = { acc[mi][ni][2] + bv0, acc[mi][ni][3] + bv1 };
            if (RELU) {
                v0.x = fmaxf(v0.x, 0.f); v0.y = fmaxf(v0.y, 0.f);
                v1.x = fmaxf(v1.x, 0.f); v1.y = fmaxf(v1.y, 0.f);
            }
            *reinterpret_cast<float2*>(&C[(size_t)r0 * ldc + c]) = v0;
            *reinterpret_cast<float2*>(&C[(size_t)(r0 + 8) * ldc + c]) = v1;
        }
    }
}

// ---------------- reduce MGT split-K partials (elementwise) ----------------
__global__ void mgt_reduce_kernel() {
    size_t i = (size_t)blockIdx.x * 256 + threadIdx.x;   // 0 .. 1024*512-1
    float s = 0.f;
    #pragma unroll
    for (int p = 0; p < NSPLIT; p++) s += g_part[(size_t)p * (1024 * CH) + i];
    g_MGT[i] = s;
}

// ---------------- SGEMM (SIMT fp32) — used only for ex -----------------------
#define BM 128
#define BN 128
#define BK 16
template<bool HASBIAS, bool RELU, bool NGUARD>
__global__ void __launch_bounds__(256, 2)
sgemm2(const float* __restrict__ A, const float* __restrict__ B,
       const float* __restrict__ bias, float* __restrict__ C,
       int M, int N, int K, int lda, int ldb, int ldc) {
    __shared__ float As[2][BK][BM];
    __shared__ float Bs[2][BK][BN];
    const int tid = threadIdx.x;
    const int m0 = blockIdx.y * BM;
    const int n0 = blockIdx.x * BN;

    const int tm = (tid / 16) * 8;
    const int tn = (tid % 16) * 8;
    const int am = tid >> 1;
    const int ak = (tid & 1) * 8;

    float acc[8][8];
    #pragma unroll
    for (int i = 0; i < 8; i++)
        #pragma unroll
        for (int j = 0; j < 8; j++) acc[i][j] = 0.f;

    float4 pa0, pa1, pb0, pb1;
    float  pbs[8];
    const int bf0 = tid;
    const int bf1 = tid + 256;
    const int bk0 = bf0 >> 5, bn0c = (bf0 & 31) * 4;
    const int bk1 = bf1 >> 5, bn1c = (bf1 & 31) * 4;

    {
        pa0 = *reinterpret_cast<const float4*>(&A[(size_t)(m0 + am) * lda + ak]);
        pa1 = *reinterpret_cast<const float4*>(&A[(size_t)(m0 + am) * lda + ak + 4]);
        if (!NGUARD) {
            pb0 = *reinterpret_cast<const float4*>(&B[(size_t)bk0 * ldb + n0 + bn0c]);
            pb1 = *reinterpret_cast<const float4*>(&B[(size_t)bk1 * ldb + n0 + bn1c]);
        } else {
            #pragma unroll
            for (int t = 0; t < 4; t++) {
                int gn0 = n0 + bn0c + t, gn1 = n0 + bn1c + t;
                pbs[t]     = (gn0 < N) ? B[(size_t)bk0 * ldb + gn0] : 0.f;
                pbs[t + 4] = (gn1 < N) ? B[(size_t)bk1 * ldb + gn1] : 0.f;
            }
        }
    }
    As[0][ak + 0][am] = pa0.x; As[0][ak + 1][am] = pa0.y;
    As[0][ak + 2][am] = pa0.z; As[0][ak + 3][am] = pa0.w;
    As[0][ak + 4][am] = pa1.x; As[0][ak + 5][am] = pa1.y;
    As[0][ak + 6][am] = pa1.z; As[0][ak + 7][am] = pa1.w;
    if (!NGUARD) {
        *reinterpret_cast<float4*>(&Bs[0][bk0][bn0c]) = pb0;
        *reinterpret_cast<float4*>(&Bs[0][bk1][bn1c]) = pb1;
    } else {
        #pragma unroll
        for (int t = 0; t < 4; t++) {
            Bs[0][bk0][bn0c + t] = pbs[t];
            Bs[0][bk1][bn1c + t] = pbs[t + 4];
        }
    }
    __syncthreads();

    int buf = 0;
    for (int k0 = 0; k0 < K; k0 += BK) {
        bool more = (k0 + BK) < K;
        if (more) {
            int kn = k0 + BK;
            pa0 = *reinterpret_cast<const float4*>(&A[(size_t)(m0 + am) * lda + kn + ak]);
            pa1 = *reinterpret_cast<const float4*>(&A[(size_t)(m0 + am) * lda + kn + ak + 4]);
            if (!NGUARD) {
                pb0 = *reinterpret_cast<const float4*>(&B[(size_t)(kn + bk0) * ldb + n0 + bn0c]);
                pb1 = *reinterpret_cast<const float4*>(&B[(size_t)(kn + bk1) * ldb + n0 + bn1c]);
            } else {
                #pragma unroll
                for (int t = 0; t < 4; t++) {
                    int gn0 = n0 + bn0c + t, gn1 = n0 + bn1c + t;
                    pbs[t]     = (gn0 < N) ? B[(size_t)(kn + bk0) * ldb + gn0] : 0.f;
                    pbs[t + 4] = (gn1 < N) ? B[(size_t)(kn + bk1) * ldb + gn1] : 0.f;
                }
            }
        }
        #pragma unroll
        for (int kk = 0; kk < BK; kk++) {
            float ar[8], br[8];
            float4 a0 = *reinterpret_cast<const float4*>(&As[buf][kk][tm]);
            float4 a1 = *reinterpret_cast<const float4*>(&As[buf][kk][tm + 4]);
            ar[0]=a0.x; ar[1]=a0.y; ar[2]=a0.z; ar[3]=a0.w;
            ar[4]=a1.x; ar[5]=a1.y; ar[6]=a1.z; ar[7]=a1.w;
            float4 b0 = *reinterpret_cast<const float4*>(&Bs[buf][kk][tn]);
            float4 b1 = *reinterpret_cast<const float4*>(&Bs[buf][kk][tn + 4]);
            br[0]=b0.x; br[1]=b0.y; br[2]=b0.z; br[3]=b0.w;
            br[4]=b1.x; br[5]=b1.y; br[6]=b1.z; br[7]=b1.w;
            #pragma unroll
            for (int i = 0; i < 8; i++)
                #pragma unroll
                for (int j = 0; j < 8; j++)
                    acc[i][j] += ar[i] * br[j];
        }
        if (more) {
            int nb = buf ^ 1;
            As[nb][ak + 0][am] = pa0.x; As[nb][ak + 1][am] = pa0.y;
            As[nb][ak + 2][am] = pa0.z; As[nb][ak + 3][am] = pa0.w;
            As[nb][ak + 4][am] = pa1.x; As[nb][ak + 5][am] = pa1.y;
            As[nb][ak + 6][am] = pa1.z; As[nb][ak + 7][am] = pa1.w;
            if (!NGUARD) {
                *reinterpret_cast<float4*>(&Bs[nb][bk0][bn0c]) = pb0;
                *reinterpret_cast<float4*>(&Bs[nb][bk1][bn1c]) = pb1;
            } else {
                #pragma unroll
                for (int t = 0; t < 4; t++) {
                    Bs[nb][bk0][bn0c + t] = pbs[t];
                    Bs[nb][bk1][bn1c + t] = pbs[t + 4];
                }
            }
            __syncthreads();
            buf = nb;
        }
    }

    #pragma unroll
    for (int i = 0; i < 8; i++) {
        int gm = m0 + tm + i;
        #pragma unroll
        for (int j = 0; j < 8; j++) {
            int gn = n0 + tn + j;
            if (!NGUARD || gn < N) {
                float v = acc[i][j];
                if (HASBIAS) v += bias[gn];
                if (RELU)    v = fmaxf(v, 0.f);
                C[(size_t)gm * ldc + gn] = v;
            }
        }
    }
}

// =================== mma.sync tf32 GEMM: SU = h1 @ MGT^T + bias ==============
#define AS_STR 136
#define BS_STR 20
__global__ void __launch_bounds__(256, 2)
su_hmma_kernel(const float* __restrict__ A, const float* __restrict__ Bt,
               const float* __restrict__ bias, float* __restrict__ C) {
    __shared__ __align__(16) uint32_t As[2][16][AS_STR];
    __shared__ __align__(16) uint32_t Bs[2][128][BS_STR];
    const int tid  = threadIdx.x;
    const int lane = tid & 31;
    const int wid  = tid >> 5;
    const int m0 = blockIdx.y * 128;
    const int n0 = blockIdx.x * 128;
    const int wm = (wid & 3) * 32;
    const int wn = (wid >> 2) * 64;
    const int lq = lane >> 2;
    const int lr = lane & 3;

    float acc[2][8][4];
    #pragma unroll
    for (int mi = 0; mi < 2; mi++)
        #pragma unroll
        for (int ni = 0; ni < 8; ni++)
            #pragma unroll
            for (int j = 0; j < 4; j++) acc[mi][ni][j] = 0.f;

    const int am = tid >> 1;
    const int ak = (tid & 1) * 8;
    const int brow = tid >> 2;
    const int bc4 = (tid & 3) * 4;

    float4 pa0, pa1, pb0, pb1;

    pa0 = *reinterpret_cast<const float4*>(&A[(size_t)(m0 + am) * 1024 + ak]);
    pa1 = *reinterpret_cast<const float4*>(&A[(size_t)(m0 + am) * 1024 + ak + 4]);
    pb0 = *reinterpret_cast<const float4*>(&Bt[(size_t)(n0 + brow) * 512 + bc4]);
    pb1 = *reinterpret_cast<const float4*>(&Bt[(size_t)(n0 + brow + 64) * 512 + bc4]);
    {
        As[0][ak + 0][am] = f2tf32(pa0.x); As[0][ak + 1][am] = f2tf32(pa0.y);
        As[0][ak + 2][am] = f2tf32(pa0.z); As[0][ak + 3][am] = f2tf32(pa0.w);
        As[0][ak + 4][am] = f2tf32(pa1.x); As[0][ak + 5][am] = f2tf32(pa1.y);
        As[0][ak + 6][am] = f2tf32(pa1.z); As[0][ak + 7][am] = f2tf32(pa1.w);
        uint4 u0 = { f2tf32(pb0.x), f2tf32(pb0.y), f2tf32(pb0.z), f2tf32(pb0.w) };
        uint4 u1 = { f2tf32(pb1.x), f2tf32(pb1.y), f2tf32(pb1.z), f2tf32(pb1.w) };
        *reinterpret_cast<uint4*>(&Bs[0][brow][bc4])      = u0;
        *reinterpret_cast<uint4*>(&Bs[0][brow + 64][bc4]) = u1;
    }
    __syncthreads();

    int buf = 0;
    for (int k0 = 0; k0 < 512; k0 += 16) {
        bool more = (k0 + 16) < 512;
        if (more) {
            int kn = k0 + 16;
            pa0 = *reinterpret_cast<const float4*>(&A[(size_t)(m0 + am) * 1024 + kn + ak]);
            pa1 = *reinterpret_cast<const float4*>(&A[(size_t)(m0 + am) * 1024 + kn + ak + 4]);
            pb0 = *reinterpret_cast<const float4*>(&Bt[(size_t)(n0 + brow) * 512 + kn + bc4]);
            pb1 = *reinterpret_cast<const float4*>(&Bt[(size_t)(n0 + brow + 64) * 512 + kn + bc4]);
        }
        #pragma unroll
        for (int kh = 0; kh < 2; kh++) {
            const int kk = kh * 8;
            uint32_t af[2][4];
            #pragma unroll
            for (int mi = 0; mi < 2; mi++) {
                int mb = wm + mi * 16 + lq;
                af[mi][0] = As[buf][kk + lr][mb];
                af[mi][1] = As[buf][kk + lr][mb + 8];
                af[mi][2] = As[buf][kk + 4 + lr][mb];
                af[mi][3] = As[buf][kk + 4 + lr][mb + 8];
            }
            #pragma unroll
            for (int ni = 0; ni < 8; ni++) {
                int nb = wn + ni * 8 + lq;
                uint32_t b0 = Bs[buf][nb][kk + lr];
                uint32_t b1 = Bs[buf][nb][kk + 4 + lr];
                mma8(acc[0][ni], af[0], b0, b1);
                mma8(acc[1][ni], af[1], b0, b1);
            }
        }
        if (more) {
            int nb = buf ^ 1;
            As[nb][ak + 0][am] = f2tf32(pa0.x); As[nb][ak + 1][am] = f2tf32(pa0.y);
            As[nb][ak + 2][am] = f2tf32(pa0.z); As[nb][ak + 3][am] = f2tf32(pa0.w);
            As[nb][ak + 4][am] = f2tf32(pa1.x); As[nb][ak + 5][am] = f2tf32(pa1.y);
            As[nb][ak + 6][am] = f2tf32(pa1.z); As[nb][ak + 7][am] = f2tf32(pa1.w);
            uint4 u0 = { f2tf32(pb0.x), f2tf32(pb0.y), f2tf32(pb0.z), f2tf32(pb0.w) };
            uint4 u1 = { f2tf32(pb1.x), f2tf32(pb1.y), f2tf32(pb1.z), f2tf32(pb1.w) };
            *reinterpret_cast<uint4*>(&Bs[nb][brow][bc4])      = u0;
            *reinterpret_cast<uint4*>(&Bs[nb][brow + 64][bc4]) = u1;
            __syncthreads();
            buf = nb;
        }
    }

    #pragma unroll
    for (int mi = 0; mi < 2; mi++) {
        int r0 = m0 + wm + mi * 16 + lq;
        #pragma unroll
        for (int ni = 0; ni < 8; ni++) {
            int c = n0 + wn + ni * 8 + lr * 2;
            float bv0 = bias[c], bv1 = bias[c + 1];
            float2 v0 = { acc[mi][ni][0] + bv0, acc[mi][ni][1] + bv1 };
            float2 v1 = { acc[mi][ni][2] + bv0, acc[mi][ni][3] + bv1 };
            *reinterpret_cast<float2*>(&C[(size_t)r0 * 1024 + c]) = v0;
            *reinterpret_cast<float2*>(&C[(size_t)(r0 + 8) * 1024 + c]) = v1;
        }
    }
}

// ---------- per-row top-2 argmin + flag near-ties + diff accumulation --------
__global__ void argmin_kernel(float* __restrict__ out_ind_f) {
    __shared__ double s_q[8];
    int warp = threadIdx.x >> 5;
    int lane = threadIdx.x & 31;
    int b = blockIdx.x * 8 + warp;

    const float* su = g_SU + (size_t)b * 1024;
    const float* h  = g_h1cat + (size_t)b * 1024;

    float q = 0.f;
    #pragma unroll 4
    for (int j = lane; j < CH; j += 32)
        q += su[512 + j] * h[j];
    #pragma unroll
    for (int o = 16; o; o >>= 1) q += __shfl_xor_sync(0xFFFFFFFFu, q, o);

    float v1 = FLT_MAX, v2 = FLT_MAX;
    int   k1 = -1, k2 = -1;
    for (int k = lane; k < NUM_EMB; k += 32) {
        float v = g_e2[k] - 2.f * su[k];
        if (v < v1 || (v == v1 && k < k1)) { v2 = v1; k2 = k1; v1 = v; k1 = k; }
        else if (v < v2 || (v == v2 && k < k2)) { v2 = v; k2 = k; }
    }
    #pragma unroll
    for (int o = 16; o; o >>= 1) {
        float ov1 = __shfl_xor_sync(0xFFFFFFFFu, v1, o);
        int   ok1 = __shfl_xor_sync(0xFFFFFFFFu, k1, o);
        float ov2 = __shfl_xor_sync(0xFFFFFFFFu, v2, o);
        int   ok2 = __shfl_xor_sync(0xFFFFFFFFu, k2, o);
        if (!(ov1 == v1 && ok1 == k1)) {
            if (ov1 < v1 || (ov1 == v1 && ok1 < k1)) { v2 = v1; k2 = k1; v1 = ov1; k1 = ok1; }
            else if (ov1 < v2 || (ov1 == v2 && ok1 < k2)) { v2 = ov1; k2 = ok1; }
        }
        if (!(ov2 == v1 && ok2 == k1)) {
            if (ov2 < v1 || (ov2 == v1 && ok2 < k1)) { v2 = v1; k2 = k1; v1 = ov2; k1 = ok2; }
            else if (ov2 < v2 || (ov2 == v2 && ok2 < k2)) { v2 = ov2; k2 = ok2; }
        }
    }
    if (lane == 0) {
        g_ind[b] = k1;
        out_ind_f[b] = (float)k1;
        s_q[warp] = (double)(q + g_beta + v1);
        if (v2 - v1 < MARGIN && k2 >= 0) {
            int idx = atomicAdd(&g_nflag, 1);
            if (idx < MAXFLAG) {
                g_fb[idx] = b; g_fk1[idx] = k1; g_fk2[idx] = k2;
            }
        }
    }
    __syncthreads();
    if (threadIdx.x == 0) {
        double t = 0.0;
        #pragma unroll
        for (int i = 0; i < 8; i++) t += s_q[i];
        atomicAdd(&g_sum, t);
    }
}

// ----- refinement via M (fp64): one warp per flagged row -----
__global__ void refine_kernel(float* __restrict__ out_ind_f) {
    int nf = g_nflag; if (nf > MAXFLAG) nf = MAXFLAG;
    int f = (blockIdx.x * 256 + threadIdx.x) >> 5;
    int lane = threadIdx.x & 31;
    if (f >= nf) return;
    int b = g_fb[f];
    int k1 = g_fk1[f], k2 = g_fk2[f];
    const float* h  = g_h1cat + (size_t)b * 1024;
    const float* m1 = g_MGT + (size_t)k1 * CH;
    const float* m2 = g_MGT + (size_t)k2 * CH;
    double s = 0.0;
    #pragma unroll 4
    for (int j = lane; j < CH; j += 32)
        s += (double)h[j] * ((double)m2[j] - (double)m1[j]);
    #pragma unroll
    for (int o = 16; o; o >>= 1) s += __shfl_xor_sync(0xFFFFFFFFu, s, o);
    if (lane == 0) {
        double delta = (g_e2d[k2] - g_e2d[k1]) - 2.0 * (s + (g_cd[k2] - g_cd[k1]));
        if (delta < 0.0 || (delta == 0.0 && k2 < k1)) {
            g_ind[b] = k2;
            out_ind_f[b] = (float)k2;
        }
    }
}

// ---------------- counts (post-refinement) ----------------
__global__ void count_kernel() {
    __shared__ int hist[NUM_EMB];
    for (int i = threadIdx.x; i < NUM_EMB; i += 256) hist[i] = 0;
    __syncthreads();
    int i0 = blockIdx.x * 2048;
    for (int i = threadIdx.x; i < 2048; i += 256)
        atomicAdd(&hist[g_ind[i0 + i]], 1);
    __syncthreads();
    for (int i = threadIdx.x; i < NUM_EMB; i += 256)
        if (hist[i]) atomicAdd(&g_counts[i], hist[i]);
}

// ---------------- per-sample expert MLP decode ----------------
__global__ void decoder_kernel(const float* __restrict__ W1, const float* __restrict__ b1,
                               const float* __restrict__ W2, const float* __restrict__ b2,
                               float* __restrict__ out) {
    __shared__ float exs[8][64];
    __shared__ float hs [8][64];
    int warp = threadIdx.x >> 5;
    int lane = threadIdx.x & 31;
    int b = blockIdx.x * 8 + warp;

    exs[warp][lane]      = g_ex[(size_t)b * 64 + lane];
    exs[warp][lane + 32] = g_ex[(size_t)b * 64 + lane + 32];
    __syncwarp();

    int k = g_ind[b];
    const float* w1 = W1 + (size_t)k * 64 * 64;
    float h0 = b1[k * 64 + lane];
    float h1 = b1[k * 64 + lane + 32];
    #pragma unroll 8
    for (int i = 0; i < 64; i++) {
        float xi = exs[warp][i];
        h0 += xi * w1[i * 64 + lane];
        h1 += xi * w1[i * 64 + lane + 32];
    }
    hs[warp][lane]      = fmaxf(h0, 0.f);
    hs[warp][lane + 32] = fmaxf(h1, 0.f);
    __syncwarp();

    const float* w2 = W2 + (size_t)k * 64 * 32;
    float o = b2[k * 32 + lane];
    #pragma unroll 8
    for (int i = 0; i < 64; i++)
        o += hs[warp][i] * w2[i * 32 + lane];
    out[(size_t)b * 32 + lane] = o;
}

// ---------------- finalize scalars ----------------
__global__ void finalize_kernel(float* __restrict__ out) {
    __shared__ float red[512];
    int k = threadIdx.x;
    float p = (float)g_counts[k] / (float)BATCH;
    red[k] = -p * logf(p + 1e-10f);
    __syncthreads();
    for (int s = 256; s; s >>= 1) {
        if (k < s) red[k] += red[k + s];
        __syncthreads();
    }
    if (k == 0) {
        out[OUT_DIFF] = (float)(g_sum / ((double)BATCH * (double)EMBED_D));
        out[OUT_PERP] = expf(red[0]);
    }
}

// ---------------- launch ----------------
extern "C" void kernel_launch(void* const* d_in, const int* in_sizes, int n_in,
                              void* d_out, int out_size) {
    const float* x     = (const float*)d_in[0];
    const float* Wf1   = (const float*)d_in[1];
    const float* bf1   = (const float*)d_in[2];
    const float* Wf2   = (const float*)d_in[3];
    const float* bf2   = (const float*)d_in[4];
    const float* Wx1   = (const float*)d_in[5];
    const float* bx1   = (const float*)d_in[6];
    const float* Wx2   = (const float*)d_in[7];
    const float* bx2   = (const float*)d_in[8];
    const float* embed = (const float*)d_in[9];
    const float* W1    = (const float*)d_in[10];
    const float* b1    = (const float*)d_in[11];
    const float* W2    = (const float*)d_in[12];
    const float* b2    = (const float*)d_in[13];
    float* out = (float*)d_out;

    float *p_h1cat, *p_SU, *p_ex, *p_MGT, *p_bias2, *p_part, *p_BcatT, *p_Bcat1T, *p_biascat1;
    cudaGetSymbolAddress((void**)&p_h1cat, g_h1cat);
    cudaGetSymbolAddress((void**)&p_SU,    g_SU);
    cudaGetSymbolAddress((void**)&p_ex,    g_ex);
    cudaGetSymbolAddress((void**)&p_MGT,   g_MGT);
    cudaGetSymbolAddress((void**)&p_bias2, g_bias2);
    cudaGetSymbolAddress((void**)&p_part,  g_part);
    cudaGetSymbolAddress((void**)&p_BcatT, g_BcatT);
    cudaGetSymbolAddress((void**)&p_Bcat1T,g_Bcat1T);
    cudaGetSymbolAddress((void**)&p_biascat1, g_biascat1);

    cudaFuncSetAttribute(hmma_x3<false, false, true>,
                         cudaFuncAttributeMaxDynamicSharedMemorySize, X3_SMEM_BYTES);
    cudaFuncSetAttribute(hmma_x3<true, true, false>,
                         cudaFuncAttributeMaxDynamicSharedMemorySize, X3_SMEM_BYTES);

    init_kernel<<<1, 1024>>>(bf1, bx1);
    embedT_kernel<<<dim3(EMBED_D / 32, NUM_EMB / 32), dim3(32, 8)>>>(embed);
    wf2copy_kernel<<<CH * EMBED_D / 4 / 256, 256>>>(Wf2);
    bcat1t_kernel<<<dim3(32, 4), dim3(32, 8)>>>(Wf1, Wx1);
    vq_partial_kernel<<<NCHUNKD, 512>>>(embed, bf2);
    g_partial_kernel<<<CH * NCHUNKG / 8, 256>>>(Wf2, bf2);
    vq_reduce_kernel<<<1, 512>>>();
    g_reduce_kernel<<<1, 512>>>();
    beta_kernel<<<1, 256>>>(bf2);

    // MGT = BcatT @ Wf2^T  (3xTF32 HMMA split-K 26) -> partials -> reduce
    hmma_x3<false, false, true><<<dim3(4, 8, NSPLIT), 256, X3_SMEM_BYTES>>>(
        p_BcatT, Wf2, nullptr, p_part, 1024, CH, EMBED_D, EMBED_D, EMBED_D, CH);
    mgt_reduce_kernel<<<1024 * CH / 256, 256>>>();

    // h1cat = relu(x @ [Wf1|Wx1] + [bf1|bx1])  (3xTF32 HMMA)
    hmma_x3<true, true, false><<<dim3(8, 128), 256, X3_SMEM_BYTES>>>(
        x, p_Bcat1T, p_biascat1, p_h1cat, BATCH, 1024, IN_C, IN_C, IN_C, 1024);

    // SU = h1 @ [M|G] + [c|2g]   (tf32 HMMA)
    su_hmma_kernel<<<dim3(8, 128), 256>>>(p_h1cat, p_MGT, p_bias2, p_SU);

    // ex = h1x @ Wx2 + bx2  (SIMT fp32)
    sgemm2<true, false, true><<<dim3(1, 128), 256>>>(
        p_h1cat + 512, Wx2, bx2, p_ex, BATCH, DEC_IN, CH, 1024, DEC_IN, DEC_IN);

    // top-2 argmin + near-tie flagging
    argmin_kernel<<<BATCH / 8, 256>>>(out + OUT_IND);

    // exact fp64 refinement through M (one warp per flag)
    refine_kernel<<<MAXFLAG / 8, 256>>>(out + OUT_IND);

    // counts after refinement
    count_kernel<<<BATCH / 2048, 256>>>();

    // expert decoder -> dec
    decoder_kernel<<<BATCH / 8, 256>>>(W1, b1, W2, b2, out);

    // diff + perplexity
    finalize_kernel<<<1, 512>>>(out);
}

// round 7
// speedup vs baseline: 12.9813x; 1.4202x over previous
#include <cuda_runtime.h>
#include <cuda_fp16.h>
#include <math.h>
#include <float.h>
#include <stdint.h>

// Problem dims
#define BATCH    16384
#define IN_C     128
#define CH       512
#define EMBED_D  6240
#define NUM_EMB  512
#define DEC_IN   64
#define DATA_Y   32

// Output layout (float32): dec[B*32], diff[1], embed_ind[B], perplexity[1]
#define OUT_DIFF  (BATCH * DATA_Y)
#define OUT_IND   (OUT_DIFF + 1)
#define OUT_PERP  (OUT_IND + BATCH)

#define MAXFLAG 16384
#define MARGIN  2.0f

#define NSPLIT  26
#define KCHUNK  240           // 26 * 240 = 6240  (MG GEMM split-K)
#define NCHUNKD 195
#define DCHUNK  32            // 195 * 32 = 6240  (vq fp64 prep chunks)
#define NCHUNKG 5
#define GCHUNK  1248          // 5 * 1248 = 6240  (g fp64 chunks)

// ---------------- scratch (device globals) ----------------
__device__ float  g_h1cat[BATCH * 1024];        // [h1 | h1x]
__device__ float  g_SU [BATCH * 1024];          // [s | u]
__device__ float  g_expad[BATCH * 128];         // embedded_x (padded to 128)
__device__ float  g_part[NSPLIT * 1024 * CH];   // MGT split-K partials
__device__ float  g_MGT [1024 * CH];            // row n = column n of [M|G]
__device__ float  g_BcatT[1024 * EMBED_D];      // [embed^T ; Wf2]
__device__ float  g_Bcat1T[1024 * IN_C];        // [Wf1 | Wx1]^T
__device__ float  g_Wx2Tpad[128 * CH];          // Wx2^T zero-padded to 128 rows
__device__ float  g_bx2pad[128];
__device__ float  g_biascat1[1024];             // [bf1 | bx1]
__device__ float  g_bias2[1024];                // [c | 2g]
__device__ float  g_e2[NUM_EMB];
__device__ double g_e2d[NUM_EMB];
__device__ double g_cd[NUM_EMB];
__device__ float  g_beta;
__device__ int    g_counts[NUM_EMB];
__device__ double g_sum;
__device__ int    g_ind[BATCH];
__device__ double g_pc [NCHUNKD * NUM_EMB];
__device__ double g_pe2[NCHUNKD * NUM_EMB];
__device__ double g_pg [NCHUNKG * CH];
// refinement state
__device__ int    g_nflag;
__device__ int    g_fb [MAXFLAG];
__device__ int    g_fk1[MAXFLAG];
__device__ int    g_fk2[MAXFLAG];

// ------------------------ fp16 helpers ------------------------
__device__ __forceinline__ uint32_t pack_h2(float a, float b) {
    __half2 h = __floats2half2_rn(a, b);
    return *reinterpret_cast<uint32_t*>(&h);
}
__device__ __forceinline__ void split2(float a, float b, uint32_t& hi, uint32_t& lo) {
    __half ha = __float2half_rn(a), hb = __float2half_rn(b);
    float la = a - __half2float(ha);
    float lb = b - __half2float(hb);
    __half2 h = __halves2half2(ha, hb);
    hi = *reinterpret_cast<uint32_t*>(&h);
    lo = pack_h2(la, lb);
}
__device__ __forceinline__ void mma16(float* c, const uint32_t* a,
                                      uint32_t b0, uint32_t b1) {
    asm volatile("mma.sync.aligned.m16n8k16.row.col.f32.f16.f16.f32 "
        "{%0,%1,%2,%3}, {%4,%5,%6,%7}, {%8,%9}, {%0,%1,%2,%3};"
        : "+f"(c[0]), "+f"(c[1]), "+f"(c[2]), "+f"(c[3])
        : "r"(a[0]), "r"(a[1]), "r"(a[2]), "r"(a[3]), "r"(b0), "r"(b1));
}

#define AS_STR 136
#define BS_STR 12

// =============================================================================
__global__ void init_kernel(const float* __restrict__ bf1,
                            const float* __restrict__ bx1) {
    int k = threadIdx.x;             // 0..1023
    if (k < NUM_EMB) g_counts[k] = 0;
    g_biascat1[k] = (k < 512) ? bf1[k] : bx1[k - 512];
    if (k == 0) { g_sum = 0.0; g_nflag = 0; }
}

// embed [6240][512] -> BcatT rows [0,512):  BcatT[k][d] = embed[d][k]
__global__ void embedT_kernel(const float* __restrict__ embed) {
    __shared__ float t[32][33];
    int d0 = blockIdx.x * 32;
    int k0 = blockIdx.y * 32;
    #pragma unroll
    for (int r = 0; r < 32; r += 8)
        t[threadIdx.y + r][threadIdx.x] =
            embed[(size_t)(d0 + threadIdx.y + r) * NUM_EMB + k0 + threadIdx.x];
    __syncthreads();
    #pragma unroll
    for (int r = 0; r < 32; r += 8)
        g_BcatT[(size_t)(k0 + threadIdx.y + r) * EMBED_D + d0 + threadIdx.x] =
            t[threadIdx.x][threadIdx.y + r];
}

// Wf2 [512][6240] copied into BcatT rows [512,1024)
__global__ void wf2copy_kernel(const float* __restrict__ Wf2) {
    size_t i = (size_t)blockIdx.x * 256 + threadIdx.x;   // float4 index
    reinterpret_cast<float4*>(g_BcatT + (size_t)512 * EMBED_D)[i] =
        reinterpret_cast<const float4*>(Wf2)[i];
}

// Bcat1T[n][k] = (n<512 ? Wf1[k][n] : Wx1[k][n-512])
__global__ void bcat1t_kernel(const float* __restrict__ Wf1,
                              const float* __restrict__ Wx1) {
    __shared__ float t[32][33];
    int n0 = blockIdx.x * 32;
    int k0 = blockIdx.y * 32;
    #pragma unroll
    for (int r = 0; r < 32; r += 8) {
        int k = k0 + threadIdx.y + r;
        int n = n0 + threadIdx.x;
        t[threadIdx.y + r][threadIdx.x] =
            (n < 512) ? Wf1[(size_t)k * 512 + n] : Wx1[(size_t)k * 512 + n - 512];
    }
    __syncthreads();
    #pragma unroll
    for (int r = 0; r < 32; r += 8)
        g_Bcat1T[(size_t)(n0 + threadIdx.y + r) * IN_C + k0 + threadIdx.x] =
            t[threadIdx.x][threadIdx.y + r];
}

// Wx2 [512][64] -> Wx2Tpad [128][512] (rows 64..127 zero); bx2 pad
__global__ void wx2pad_kernel(const float* __restrict__ Wx2,
                              const float* __restrict__ bx2) {
    int i = blockIdx.x * 256 + threadIdx.x;    // 0 .. 128*512-1
    int n = i >> 9;
    int k = i & 511;
    g_Wx2Tpad[i] = (n < 64) ? Wx2[(size_t)k * 64 + n] : 0.f;
    if (i < 128) g_bx2pad[i] = (i < 64) ? bx2[i] : 0.f;
}

// chunked fp64 partials for c[k], e2[k]
__global__ void vq_partial_kernel(const float* __restrict__ embed,
                                  const float* __restrict__ bf2) {
    int k = threadIdx.x;
    int d0 = blockIdx.x * DCHUNK;
    double cc = 0.0, ee = 0.0;
    for (int d = d0; d < d0 + DCHUNK; d++) {
        double e = (double)embed[(size_t)d * NUM_EMB + k];
        cc += (double)bf2[d] * e;
        ee += e * e;
    }
    g_pc [blockIdx.x * NUM_EMB + k] = cc;
    g_pe2[blockIdx.x * NUM_EMB + k] = ee;
}

__global__ void vq_reduce_kernel() {
    int k = threadIdx.x;
    double cc = 0.0, ee = 0.0;
    for (int s = 0; s < NCHUNKD; s++) {
        cc += g_pc [s * NUM_EMB + k];
        ee += g_pe2[s * NUM_EMB + k];
    }
    g_bias2[k] = (float)cc;
    g_cd[k]  = cc;
    g_e2[k]  = (float)ee;
    g_e2d[k] = ee;
}

// g partials: warp per (row i, chunk c) directly on Wf2 (coalesced)
__global__ void g_partial_kernel(const float* __restrict__ Wf2,
                                 const float* __restrict__ bf2) {
    int gw = blockIdx.x * 8 + (threadIdx.x >> 5);
    int lane = threadIdx.x & 31;
    int i = gw % CH;
    int c = gw / CH;
    const float* w = Wf2 + (size_t)i * EMBED_D + c * GCHUNK;
    const float* b = bf2 + c * GCHUNK;
    double s = 0.0;
    #pragma unroll 4
    for (int t = lane; t < GCHUNK; t += 32)
        s += (double)w[t] * (double)b[t];
    #pragma unroll
    for (int o = 16; o; o >>= 1) s += __shfl_xor_sync(0xFFFFFFFFu, s, o);
    if (lane == 0) g_pg[c * CH + i] = s;
}

__global__ void g_reduce_kernel() {
    int i = threadIdx.x;
    double s = 0.0;
    #pragma unroll
    for (int c = 0; c < NCHUNKG; c++) s += g_pg[c * CH + i];
    g_bias2[CH + i] = (float)(2.0 * s);
}

__global__ void beta_kernel(const float* __restrict__ bf2) {
    __shared__ double red[256];
    double s = 0.0;
    for (int d = threadIdx.x; d < EMBED_D; d += 256) { double v = bf2[d]; s += v * v; }
    red[threadIdx.x] = s;
    __syncthreads();
    for (int t = 128; t; t >>= 1) {
        if (threadIdx.x < t) red[threadIdx.x] += red[threadIdx.x + t];
        __syncthreads();
    }
    if (threadIdx.x == 0) g_beta = (float)red[0];
}

// ============ fp16 x3 HMMA GEMM: C = op(A @ Bt^T [+bias][relu]) ==============
// A row-major [M, lda] (K contiguous); Bt row-major [N, ldb] (= B col-major).
// Block tile 128x128, BK=16 double-buffered, 8 warps each 32x64 (m16n8k16).
// acc += Ahi*Bhi + Ahi*Blo + Alo*Bhi  (fp32-grade: ~22-bit mantissa)
template<bool HASBIAS, bool RELU, bool SPLITK>
__global__ void __launch_bounds__(256)
hmma16_x3(const float* __restrict__ A, const float* __restrict__ Bt,
          const float* __restrict__ bias, float* __restrict__ C,
          int M, int N, int K, int lda, int ldb, int ldc) {
    __shared__ uint32_t AsH[2][8][AS_STR];
    __shared__ uint32_t AsL[2][8][AS_STR];
    __shared__ uint32_t BsH[2][128][BS_STR];
    __shared__ uint32_t BsL[2][128][BS_STR];
    const int tid  = threadIdx.x;
    const int lane = tid & 31;
    const int wid  = tid >> 5;
    const int n0 = blockIdx.x * 128;
    const int m0 = blockIdx.y * 128;
    if (SPLITK) {
        A  += blockIdx.z * KCHUNK;
        Bt += blockIdx.z * KCHUNK;
        C  += (size_t)blockIdx.z * M * N;
        K = KCHUNK;
    }
    const int wm = (wid & 3) * 32;
    const int wn = (wid >> 2) * 64;
    const int lq = lane >> 2;
    const int lr = lane & 3;

    float acc[2][8][4];
    #pragma unroll
    for (int mi = 0; mi < 2; mi++)
        #pragma unroll
        for (int ni = 0; ni < 8; ni++)
            #pragma unroll
            for (int j = 0; j < 4; j++) acc[mi][ni][j] = 0.f;

    const int r0  = tid >> 2;        // 0..63 (+64 second)
    const int c4  = (tid & 3) * 4;   // k float offset
    const int kp0 = (tid & 3) * 2;   // half2 pair index

    float4 pa[2], pb[2];

    // prime chunk 0
    #pragma unroll
    for (int i = 0; i < 2; i++) {
        pa[i] = *reinterpret_cast<const float4*>(&A [(size_t)(m0 + r0 + 64 * i) * lda + c4]);
        pb[i] = *reinterpret_cast<const float4*>(&Bt[(size_t)(n0 + r0 + 64 * i) * ldb + c4]);
    }
    #pragma unroll
    for (int i = 0; i < 2; i++) {
        int r = r0 + 64 * i;
        uint32_t h01, h23, l01, l23;
        split2(pa[i].x, pa[i].y, h01, l01);
        split2(pa[i].z, pa[i].w, h23, l23);
        AsH[0][kp0][r] = h01; AsH[0][kp0 + 1][r] = h23;
        AsL[0][kp0][r] = l01; AsL[0][kp0 + 1][r] = l23;
        split2(pb[i].x, pb[i].y, h01, l01);
        split2(pb[i].z, pb[i].w, h23, l23);
        BsH[0][r][kp0] = h01; BsH[0][r][kp0 + 1] = h23;
        BsL[0][r][kp0] = l01; BsL[0][r][kp0 + 1] = l23;
    }
    __syncthreads();

    int buf = 0;
    for (int k0 = 0; k0 < K; k0 += 16) {
        bool more = (k0 + 16) < K;
        if (more) {
            int kn = k0 + 16;
            #pragma unroll
            for (int i = 0; i < 2; i++) {
                pa[i] = *reinterpret_cast<const float4*>(&A [(size_t)(m0 + r0 + 64 * i) * lda + kn + c4]);
                pb[i] = *reinterpret_cast<const float4*>(&Bt[(size_t)(n0 + r0 + 64 * i) * ldb + kn + c4]);
            }
        }
        // fragments
        uint32_t ah[2][4], al[2][4];
        #pragma unroll
        for (int mi = 0; mi < 2; mi++) {
            int mb = wm + mi * 16 + lq;
            ah[mi][0] = AsH[buf][lr][mb];     ah[mi][1] = AsH[buf][lr][mb + 8];
            ah[mi][2] = AsH[buf][lr + 4][mb]; ah[mi][3] = AsH[buf][lr + 4][mb + 8];
            al[mi][0] = AsL[buf][lr][mb];     al[mi][1] = AsL[buf][lr][mb + 8];
            al[mi][2] = AsL[buf][lr + 4][mb]; al[mi][3] = AsL[buf][lr + 4][mb + 8];
        }
        #pragma unroll
        for (int ni = 0; ni < 8; ni++) {
            int nb = wn + ni * 8 + lq;
            uint32_t bh0 = BsH[buf][nb][lr], bh1 = BsH[buf][nb][lr + 4];
            uint32_t bl0 = BsL[buf][nb][lr], bl1 = BsL[buf][nb][lr + 4];
            mma16(acc[0][ni], ah[0], bh0, bh1);
            mma16(acc[0][ni], ah[0], bl0, bl1);
            mma16(acc[0][ni], al[0], bh0, bh1);
            mma16(acc[1][ni], ah[1], bh0, bh1);
            mma16(acc[1][ni], ah[1], bl0, bl1);
            mma16(acc[1][ni], al[1], bh0, bh1);
        }
        if (more) {
            int nb2 = buf ^ 1;
            __syncthreads();   // all reads of current buffer done before overwrite? (separate buffers; sync protects reuse)
            #pragma unroll
            for (int i = 0; i < 2; i++) {
                int r = r0 + 64 * i;
                uint32_t h01, h23, l01, l23;
                split2(pa[i].x, pa[i].y, h01, l01);
                split2(pa[i].z, pa[i].w, h23, l23);
                AsH[nb2][kp0][r] = h01; AsH[nb2][kp0 + 1][r] = h23;
                AsL[nb2][kp0][r] = l01; AsL[nb2][kp0 + 1][r] = l23;
                split2(pb[i].x, pb[i].y, h01, l01);
                split2(pb[i].z, pb[i].w, h23, l23);
                BsH[nb2][r][kp0] = h01; BsH[nb2][r][kp0 + 1] = h23;
                BsL[nb2][r][kp0] = l01; BsL[nb2][r][kp0 + 1] = l23;
            }
            __syncthreads();
            buf = nb2;
        }
    }

    // epilogue
    #pragma unroll
    for (int mi = 0; mi < 2; mi++) {
        int r0o = m0 + wm + mi * 16 + lq;
        #pragma unroll
        for (int ni = 0; ni < 8; ni++) {
            int c = n0 + wn + ni * 8 + lr * 2;
            float bv0 = HASBIAS ? bias[c] : 0.f;
            float bv1 = HASBIAS ? bias[c + 1] : 0.f;
            float2 v0 = { acc[mi][ni][0] + bv0, acc[mi][ni][1] + bv1 };
            float2 v1 = { acc[mi][ni][2] + bv0, acc[mi][ni][3] + bv1 };
            if (RELU) {
                v0.x = fmaxf(v0.x, 0.f); v0.y = fmaxf(v0.y, 0.f);
                v1.x = fmaxf(v1.x, 0.f); v1.y = fmaxf(v1.y, 0.f);
            }
            *reinterpret_cast<float2*>(&C[(size_t)r0o * ldc + c]) = v0;
            *reinterpret_cast<float2*>(&C[(size_t)(r0o + 8) * ldc + c]) = v1;
        }
    }
}

// ---------------- reduce MGT split-K partials (elementwise) ----------------
__global__ void mgt_reduce_kernel() {
    size_t i = (size_t)blockIdx.x * 256 + threadIdx.x;
    float s = 0.f;
    #pragma unroll
    for (int p = 0; p < NSPLIT; p++) s += g_part[(size_t)p * (1024 * CH) + i];
    g_MGT[i] = s;
}

// ============ fp16 1x HMMA GEMM: SU = h1 @ MGT^T + bias (noise OK) ===========
__global__ void __launch_bounds__(256, 2)
su16_kernel(const float* __restrict__ A, const float* __restrict__ Bt,
            const float* __restrict__ bias, float* __restrict__ C) {
    __shared__ uint32_t As[2][8][AS_STR];
    __shared__ uint32_t Bs[2][128][BS_STR];
    const int tid  = threadIdx.x;
    const int lane = tid & 31;
    const int wid  = tid >> 5;
    const int n0 = blockIdx.x * 128;
    const int m0 = blockIdx.y * 128;
    const int wm = (wid & 3) * 32;
    const int wn = (wid >> 2) * 64;
    const int lq = lane >> 2;
    const int lr = lane & 3;

    float acc[2][8][4];
    #pragma unroll
    for (int mi = 0; mi < 2; mi++)
        #pragma unroll
        for (int ni = 0; ni < 8; ni++)
            #pragma unroll
            for (int j = 0; j < 4; j++) acc[mi][ni][j] = 0.f;

    const int r0  = tid >> 2;
    const int c4  = (tid & 3) * 4;
    const int kp0 = (tid & 3) * 2;

    float4 pa[2], pb[2];
    #pragma unroll
    for (int i = 0; i < 2; i++) {
        pa[i] = *reinterpret_cast<const float4*>(&A [(size_t)(m0 + r0 + 64 * i) * 1024 + c4]);
        pb[i] = *reinterpret_cast<const float4*>(&Bt[(size_t)(n0 + r0 + 64 * i) * 512 + c4]);
    }
    #pragma unroll
    for (int i = 0; i < 2; i++) {
        int r = r0 + 64 * i;
        As[0][kp0][r]     = pack_h2(pa[i].x, pa[i].y);
        As[0][kp0 + 1][r] = pack_h2(pa[i].z, pa[i].w);
        Bs[0][r][kp0]     = pack_h2(pb[i].x, pb[i].y);
        Bs[0][r][kp0 + 1] = pack_h2(pb[i].z, pb[i].w);
    }
    __syncthreads();

    int buf = 0;
    for (int k0 = 0; k0 < 512; k0 += 16) {
        bool more = (k0 + 16) < 512;
        if (more) {
            int kn = k0 + 16;
            #pragma unroll
            for (int i = 0; i < 2; i++) {
                pa[i] = *reinterpret_cast<const float4*>(&A [(size_t)(m0 + r0 + 64 * i) * 1024 + kn + c4]);
                pb[i] = *reinterpret_cast<const float4*>(&Bt[(size_t)(n0 + r0 + 64 * i) * 512 + kn + c4]);
            }
        }
        uint32_t af[2][4];
        #pragma unroll
        for (int mi = 0; mi < 2; mi++) {
            int mb = wm + mi * 16 + lq;
            af[mi][0] = As[buf][lr][mb];     af[mi][1] = As[buf][lr][mb + 8];
            af[mi][2] = As[buf][lr + 4][mb]; af[mi][3] = As[buf][lr + 4][mb + 8];
        }
        #pragma unroll
        for (int ni = 0; ni < 8; ni++) {
            int nb = wn + ni * 8 + lq;
            uint32_t b0 = Bs[buf][nb][lr], b1 = Bs[buf][nb][lr + 4];
            mma16(acc[0][ni], af[0], b0, b1);
            mma16(acc[1][ni], af[1], b0, b1);
        }
        if (more) {
            int nb2 = buf ^ 1;
            #pragma unroll
            for (int i = 0; i < 2; i++) {
                int r = r0 + 64 * i;
                As[nb2][kp0][r]     = pack_h2(pa[i].x, pa[i].y);
                As[nb2][kp0 + 1][r] = pack_h2(pa[i].z, pa[i].w);
                Bs[nb2][r][kp0]     = pack_h2(pb[i].x, pb[i].y);
                Bs[nb2][r][kp0 + 1] = pack_h2(pb[i].z, pb[i].w);
            }
            __syncthreads();
            buf = nb2;
        }
    }

    #pragma unroll
    for (int mi = 0; mi < 2; mi++) {
        int r0o = m0 + wm + mi * 16 + lq;
        #pragma unroll
        for (int ni = 0; ni < 8; ni++) {
            int c = n0 + wn + ni * 8 + lr * 2;
            float bv0 = bias[c], bv1 = bias[c + 1];
            float2 v0 = { acc[mi][ni][0] + bv0, acc[mi][ni][1] + bv1 };
            float2 v1 = { acc[mi][ni][2] + bv0, acc[mi][ni][3] + bv1 };
            *reinterpret_cast<float2*>(&C[(size_t)r0o * 1024 + c]) = v0;
            *reinterpret_cast<float2*>(&C[(size_t)(r0o + 8) * 1024 + c]) = v1;
        }
    }
}

// ---------- per-row top-2 argmin + flag near-ties + diff accumulation --------
__global__ void argmin_kernel(float* __restrict__ out_ind_f) {
    __shared__ double s_q[8];
    int warp = threadIdx.x >> 5;
    int lane = threadIdx.x & 31;
    int b = blockIdx.x * 8 + warp;

    const float* su = g_SU + (size_t)b * 1024;
    const float* h  = g_h1cat + (size_t)b * 1024;

    float q = 0.f;
    #pragma unroll 4
    for (int j = lane; j < CH; j += 32)
        q += su[512 + j] * h[j];
    #pragma unroll
    for (int o = 16; o; o >>= 1) q += __shfl_xor_sync(0xFFFFFFFFu, q, o);

    float v1 = FLT_MAX, v2 = FLT_MAX;
    int   k1 = -1, k2 = -1;
    for (int k = lane; k < NUM_EMB; k += 32) {
        float v = g_e2[k] - 2.f * su[k];
        if (v < v1 || (v == v1 && k < k1)) { v2 = v1; k2 = k1; v1 = v; k1 = k; }
        else if (v < v2 || (v == v2 && k < k2)) { v2 = v; k2 = k; }
    }
    #pragma unroll
    for (int o = 16; o; o >>= 1) {
        float ov1 = __shfl_xor_sync(0xFFFFFFFFu, v1, o);
        int   ok1 = __shfl_xor_sync(0xFFFFFFFFu, k1, o);
        float ov2 = __shfl_xor_sync(0xFFFFFFFFu, v2, o);
        int   ok2 = __shfl_xor_sync(0xFFFFFFFFu, k2, o);
        if (!(ov1 == v1 && ok1 == k1)) {
            if (ov1 < v1 || (ov1 == v1 && ok1 < k1)) { v2 = v1; k2 = k1; v1 = ov1; k1 = ok1; }
            else if (ov1 < v2 || (ov1 == v2 && ok1 < k2)) { v2 = ov1; k2 = ok1; }
        }
        if (!(ov2 == v1 && ok2 == k1)) {
            if (ov2 < v1 || (ov2 == v1 && ok2 < k1)) { v2 = v1; k2 = k1; v1 = ov2; k1 = ok2; }
            else if (ov2 < v2 || (ov2 == v2 && ok2 < k2)) { v2 = ov2; k2 = ok2; }
        }
    }
    if (lane == 0) {
        g_ind[b] = k1;
        out_ind_f[b] = (float)k1;
        s_q[warp] = (double)(q + g_beta + v1);
        if (v2 - v1 < MARGIN && k2 >= 0) {
            int idx = atomicAdd(&g_nflag, 1);
            if (idx < MAXFLAG) {
                g_fb[idx] = b; g_fk1[idx] = k1; g_fk2[idx] = k2;
            }
        }
    }
    __syncthreads();
    if (threadIdx.x == 0) {
        double t = 0.0;
        #pragma unroll
        for (int i = 0; i < 8; i++) t += s_q[i];
        atomicAdd(&g_sum, t);
    }
}

// ----- refinement via M (fp64): one warp per flagged row -----
__global__ void refine_kernel(float* __restrict__ out_ind_f) {
    int nf = g_nflag; if (nf > MAXFLAG) nf = MAXFLAG;
    int f = (blockIdx.x * 256 + threadIdx.x) >> 5;
    int lane = threadIdx.x & 31;
    if (f >= nf) return;
    int b = g_fb[f];
    int k1 = g_fk1[f], k2 = g_fk2[f];
    const float* h  = g_h1cat + (size_t)b * 1024;
    const float* m1 = g_MGT + (size_t)k1 * CH;
    const float* m2 = g_MGT + (size_t)k2 * CH;
    double s = 0.0;
    #pragma unroll 4
    for (int j = lane; j < CH; j += 32)
        s += (double)h[j] * ((double)m2[j] - (double)m1[j]);
    #pragma unroll
    for (int o = 16; o; o >>= 1) s += __shfl_xor_sync(0xFFFFFFFFu, s, o);
    if (lane == 0) {
        double delta = (g_e2d[k2] - g_e2d[k1]) - 2.0 * (s + (g_cd[k2] - g_cd[k1]));
        if (delta < 0.0 || (delta == 0.0 && k2 < k1)) {
            g_ind[b] = k2;
            out_ind_f[b] = (float)k2;
        }
    }
}

// ---------------- counts (post-refinement) ----------------
__global__ void count_kernel() {
    __shared__ int hist[NUM_EMB];
    for (int i = threadIdx.x; i < NUM_EMB; i += 256) hist[i] = 0;
    __syncthreads();
    int i0 = blockIdx.x * 2048;
    for (int i = threadIdx.x; i < 2048; i += 256)
        atomicAdd(&hist[g_ind[i0 + i]], 1);
    __syncthreads();
    for (int i = threadIdx.x; i < NUM_EMB; i += 256)
        if (hist[i]) atomicAdd(&g_counts[i], hist[i]);
}

// ---------------- per-sample expert MLP decode ----------------
__global__ void decoder_kernel(const float* __restrict__ W1, const float* __restrict__ b1,
                               const float* __restrict__ W2, const float* __restrict__ b2,
                               float* __restrict__ out) {
    __shared__ float exs[8][64];
    __shared__ float hs [8][64];
    int warp = threadIdx.x >> 5;
    int lane = threadIdx.x & 31;
    int b = blockIdx.x * 8 + warp;

    exs[warp][lane]      = g_expad[(size_t)b * 128 + lane];
    exs[warp][lane + 32] = g_expad[(size_t)b * 128 + lane + 32];
    __syncwarp();

    int k = g_ind[b];
    const float* w1 = W1 + (size_t)k * 64 * 64;
    float h0 = b1[k * 64 + lane];
    float h1 = b1[k * 64 + lane + 32];
    #pragma unroll 8
    for (int i = 0; i < 64; i++) {
        float xi = exs[warp][i];
        h0 += xi * w1[i * 64 + lane];
        h1 += xi * w1[i * 64 + lane + 32];
    }
    hs[warp][lane]      = fmaxf(h0, 0.f);
    hs[warp][lane + 32] = fmaxf(h1, 0.f);
    __syncwarp();

    const float* w2 = W2 + (size_t)k * 64 * 32;
    float o = b2[k * 32 + lane];
    #pragma unroll 8
    for (int i = 0; i < 64; i++)
        o += hs[warp][i] * w2[i * 32 + lane];
    out[(size_t)b * 32 + lane] = o;
}

// ---------------- finalize scalars ----------------
__global__ void finalize_kernel(float* __restrict__ out) {
    __shared__ float red[512];
    int k = threadIdx.x;
    float p = (float)g_counts[k] / (float)BATCH;
    red[k] = -p * logf(p + 1e-10f);
    __syncthreads();
    for (int s = 256; s; s >>= 1) {
        if (k < s) red[k] += red[k + s];
        __syncthreads();
    }
    if (k == 0) {
        out[OUT_DIFF] = (float)(g_sum / ((double)BATCH * (double)EMBED_D));
        out[OUT_PERP] = expf(red[0]);
    }
}

// ---------------- launch ----------------
extern "C" void kernel_launch(void* const* d_in, const int* in_sizes, int n_in,
                              void* d_out, int out_size) {
    const float* x     = (const float*)d_in[0];
    const float* Wf1   = (const float*)d_in[1];
    const float* bf1   = (const float*)d_in[2];
    const float* Wf2   = (const float*)d_in[3];
    const float* bf2   = (const float*)d_in[4];
    const float* Wx1   = (const float*)d_in[5];
    const float* bx1   = (const float*)d_in[6];
    const float* Wx2   = (const float*)d_in[7];
    const float* bx2   = (const float*)d_in[8];
    const float* embed = (const float*)d_in[9];
    const float* W1    = (const float*)d_in[10];
    const float* b1    = (const float*)d_in[11];
    const float* W2    = (const float*)d_in[12];
    const float* b2    = (const float*)d_in[13];
    float* out = (float*)d_out;

    float *p_h1cat, *p_SU, *p_expad, *p_MGT, *p_bias2, *p_part, *p_BcatT,
          *p_Bcat1T, *p_biascat1, *p_Wx2Tpad, *p_bx2pad;
    cudaGetSymbolAddress((void**)&p_h1cat, g_h1cat);
    cudaGetSymbolAddress((void**)&p_SU,    g_SU);
    cudaGetSymbolAddress((void**)&p_expad, g_expad);
    cudaGetSymbolAddress((void**)&p_MGT,   g_MGT);
    cudaGetSymbolAddress((void**)&p_bias2, g_bias2);
    cudaGetSymbolAddress((void**)&p_part,  g_part);
    cudaGetSymbolAddress((void**)&p_BcatT, g_BcatT);
    cudaGetSymbolAddress((void**)&p_Bcat1T,g_Bcat1T);
    cudaGetSymbolAddress((void**)&p_biascat1, g_biascat1);
    cudaGetSymbolAddress((void**)&p_Wx2Tpad, g_Wx2Tpad);
    cudaGetSymbolAddress((void**)&p_bx2pad,  g_bx2pad);

    // 1..3: prep needed by MG
    init_kernel<<<1, 1024>>>(bf1, bx1);
    embedT_kernel<<<dim3(EMBED_D / 32, NUM_EMB / 32), dim3(32, 8)>>>(embed);
    wf2copy_kernel<<<CH * EMBED_D / 4 / 256, 256>>>(Wf2);

    // 4: MGT = BcatT @ Wf2^T (fp16 x3, split-K 26)  [profiled launch slot]
    hmma16_x3<false, false, true><<<dim3(4, 8, NSPLIT), 256>>>(
        p_BcatT, Wf2, nullptr, p_part, 1024, CH, EMBED_D, EMBED_D, EMBED_D, CH);
    mgt_reduce_kernel<<<1024 * CH / 256, 256>>>();

    // remaining prep
    bcat1t_kernel<<<dim3(32, 4), dim3(32, 8)>>>(Wf1, Wx1);
    wx2pad_kernel<<<128 * CH / 256, 256>>>(Wx2, bx2);
    vq_partial_kernel<<<NCHUNKD, 512>>>(embed, bf2);
    g_partial_kernel<<<CH * NCHUNKG / 8, 256>>>(Wf2, bf2);
    vq_reduce_kernel<<<1, 512>>>();
    g_reduce_kernel<<<1, 512>>>();
    beta_kernel<<<1, 256>>>(bf2);

    // h1cat = relu(x @ [Wf1|Wx1] + [bf1|bx1])  (fp16 x3)
    hmma16_x3<true, true, false><<<dim3(8, 128), 256>>>(
        x, p_Bcat1T, p_biascat1, p_h1cat, BATCH, 1024, IN_C, IN_C, IN_C, 1024);

    // SU = h1 @ [M|G] + [c|2g]  (fp16 1x; noise absorbed by refinement)
    su16_kernel<<<dim3(8, 128), 256>>>(p_h1cat, p_MGT, p_bias2, p_SU);

    // ex = h1x @ Wx2 + bx2  (fp16 x3, N padded to 128)
    hmma16_x3<true, false, false><<<dim3(1, 128), 256>>>(
        p_h1cat + 512, p_Wx2Tpad, p_bx2pad, p_expad, BATCH, 128, CH, 1024, CH, 128);

    // top-2 argmin + near-tie flagging
    argmin_kernel<<<BATCH / 8, 256>>>(out + OUT_IND);

    // exact fp64 refinement through M (one warp per flag)
    refine_kernel<<<MAXFLAG / 8, 256>>>(out + OUT_IND);

    // counts after refinement
    count_kernel<<<BATCH / 2048, 256>>>();

    // expert decoder -> dec
    decoder_kernel<<<BATCH / 8, 256>>>(W1, b1, W2, b2, out);

    // diff + perplexity
    finalize_kernel<<<1, 512>>>(out);
}